// round 6
// baseline (speedup 1.0000x reference)
#include <cuda_runtime.h>
#include <cuda_bf16.h>
#include <math.h>
#include <stdint.h>

#define SQ 4096
#define DM 1024
#define NH 16
#define DHD 64
#define FF 4096
#define QKVN 3072

typedef __nv_bfloat16 bf16;

// Scratch (device globals — no runtime allocation allowed)
__device__ bf16 g_yh [SQ*DM],   g_yl [SQ*DM];    // LN1 out split
__device__ bf16 g_qkvh[SQ*QKVN],g_qkvl[SQ*QKVN]; // packed q|k|v split
__device__ bf16 g_ctxh[SQ*DM],  g_ctxl[SQ*DM];   // attention out split
__device__ bf16 g_y2h[SQ*DM],   g_y2l[SQ*DM];    // LN2 out split
__device__ bf16 g_hh [SQ*FF],   g_hl [SQ*FF];    // GELU out split
// transposed split weights [N][K]
__device__ bf16 g_wqkvh[QKVN*DM], g_wqkvl[QKVN*DM];
__device__ bf16 g_woh [DM*DM],  g_wol [DM*DM];
__device__ bf16 g_w1h [FF*DM],  g_w1l [FF*DM];
__device__ bf16 g_w2h [DM*FF],  g_w2l [DM*FF];
__device__ float g_bqkv[QKVN];

// ===========================================================================
// Helpers
// ===========================================================================
__device__ __forceinline__ uint32_t smem_u32(const void* p) {
    uint32_t a;
    asm("{ .reg .u64 t; cvta.to.shared.u64 t, %1; cvt.u32.u64 %0, t; }" : "=r"(a) : "l"(p));
    return a;
}
__device__ __forceinline__ void ldsm4(uint32_t* r, uint32_t addr) {
    asm volatile("ldmatrix.sync.aligned.m8n8.x4.shared.b16 {%0,%1,%2,%3}, [%4];"
        : "=r"(r[0]), "=r"(r[1]), "=r"(r[2]), "=r"(r[3]) : "r"(addr));
}
__device__ __forceinline__ void ldsm4t(uint32_t* r, uint32_t addr) {
    asm volatile("ldmatrix.sync.aligned.m8n8.x4.trans.shared.b16 {%0,%1,%2,%3}, [%4];"
        : "=r"(r[0]), "=r"(r[1]), "=r"(r[2]), "=r"(r[3]) : "r"(addr));
}
__device__ __forceinline__ void mma16816(float* c, const uint32_t* a,
                                         uint32_t b0, uint32_t b1) {
    asm volatile("mma.sync.aligned.m16n8k16.row.col.f32.bf16.bf16.f32 "
        "{%0,%1,%2,%3}, {%4,%5,%6,%7}, {%8,%9}, {%0,%1,%2,%3};"
        : "+f"(c[0]), "+f"(c[1]), "+f"(c[2]), "+f"(c[3])
        : "r"(a[0]), "r"(a[1]), "r"(a[2]), "r"(a[3]), "r"(b0), "r"(b1));
}
__device__ __forceinline__ void cpasync16(uint32_t dst, const void* src) {
    asm volatile("cp.async.cg.shared.global [%0], [%1], 16;" :: "r"(dst), "l"(src));
}
#define CP_COMMIT() asm volatile("cp.async.commit_group;" ::: "memory")
#define CP_WAIT(n)  asm volatile("cp.async.wait_group %0;" :: "n"(n) : "memory")

__device__ __forceinline__ void split_pack(float x0, float x1, uint32_t& hp, uint32_t& lp) {
    bf16 h0 = __float2bfloat16_rn(x0);
    bf16 h1 = __float2bfloat16_rn(x1);
    bf16 l0 = __float2bfloat16_rn(x0 - __bfloat162float(h0));
    bf16 l1 = __float2bfloat16_rn(x1 - __bfloat162float(h1));
    hp = (uint32_t)__bfloat16_as_ushort(h0) | ((uint32_t)__bfloat16_as_ushort(h1) << 16);
    lp = (uint32_t)__bfloat16_as_ushort(l0) | ((uint32_t)__bfloat16_as_ushort(l1) << 16);
}
__device__ __forceinline__ uint32_t pack_bf16(float x0, float x1) {
    __nv_bfloat162 p = __floats2bfloat162_rn(x0, x1);
    return *(uint32_t*)&p;
}

// ---------------------------------------------------------------------------
// Weight transpose + split: W[K][N] fp32 -> Th/Tl[N][K] bf16
// ---------------------------------------------------------------------------
__global__ __launch_bounds__(256) void wconv(const float* __restrict__ W,
                                             bf16* __restrict__ Th,
                                             bf16* __restrict__ Tl,
                                             int K, int N)
{
    __shared__ float tile[32][33];
    const int n0 = blockIdx.x * 32, k0 = blockIdx.y * 32;
    const int t = threadIdx.x;
#pragma unroll
    for (int i = 0; i < 4; i++) {
        int idx = t + 256 * i;
        int kr = idx >> 5, nc = idx & 31;
        tile[kr][nc] = W[(size_t)(k0 + kr) * N + n0 + nc];
    }
    __syncthreads();
#pragma unroll
    for (int i = 0; i < 2; i++) {
        int idx = t + 256 * i;
        int n = idx >> 4, c = idx & 15;
        uint32_t hp, lp;
        split_pack(tile[2 * c][n], tile[2 * c + 1][n], hp, lp);
        size_t o = (size_t)(n0 + n) * K + k0 + 2 * c;
        *(uint32_t*)(Th + o) = hp;
        *(uint32_t*)(Tl + o) = lp;
    }
}

__global__ void pack_bias(const float* __restrict__ bq, const float* __restrict__ bk,
                          const float* __restrict__ bv, float* __restrict__ dst)
{
    int i = blockIdx.x * 256 + threadIdx.x;
    if (i < 1024) dst[i] = bq[i];
    else if (i < 2048) dst[i] = bk[i - 1024];
    else if (i < QKVN) dst[i] = bv[i - 2048];
}

// ---------------------------------------------------------------------------
// LayerNorm -> split bf16. One block/row, 256 threads.
// ---------------------------------------------------------------------------
__global__ __launch_bounds__(256) void ln_split(const float* __restrict__ x,
                                                const float* __restrict__ sc,
                                                const float* __restrict__ bi,
                                                bf16* __restrict__ yh,
                                                bf16* __restrict__ yl)
{
    int row = blockIdx.x;
    const float* xr = x + (size_t)row * DM;
    int t = threadIdx.x;

    float4 v = *(const float4*)(xr + 4 * t);
    float s = v.x + v.y + v.z + v.w;

    __shared__ float red[8];
#pragma unroll
    for (int o = 16; o > 0; o >>= 1) s += __shfl_xor_sync(0xffffffffu, s, o);
    if ((t & 31) == 0) red[t >> 5] = s;
    __syncthreads();
    if (t < 32) {
        float r = (t < 8) ? red[t] : 0.f;
#pragma unroll
        for (int o = 4; o > 0; o >>= 1) r += __shfl_xor_sync(0xffffffffu, r, o);
        if (t == 0) red[0] = r;
    }
    __syncthreads();
    float mu = red[0] * (1.0f / DM);
    __syncthreads();

    float d0 = v.x - mu, d1 = v.y - mu, d2 = v.z - mu, d3 = v.w - mu;
    float vs = d0 * d0 + d1 * d1 + d2 * d2 + d3 * d3;
#pragma unroll
    for (int o = 16; o > 0; o >>= 1) vs += __shfl_xor_sync(0xffffffffu, vs, o);
    if ((t & 31) == 0) red[t >> 5] = vs;
    __syncthreads();
    if (t < 32) {
        float r = (t < 8) ? red[t] : 0.f;
#pragma unroll
        for (int o = 4; o > 0; o >>= 1) r += __shfl_xor_sync(0xffffffffu, r, o);
        if (t == 0) red[0] = r;
    }
    __syncthreads();
    float rstd = rsqrtf(red[0] * (1.0f / DM) + 1e-6f);

    float4 s4 = *(const float4*)(sc + 4 * t);
    float4 b4 = *(const float4*)(bi + 4 * t);
    float n0 = d0 * rstd * s4.x + b4.x;
    float n1 = d1 * rstd * s4.y + b4.y;
    float n2 = d2 * rstd * s4.z + b4.z;
    float n3 = d3 * rstd * s4.w + b4.w;
    uint32_t h0, l0, h1, l1;
    split_pack(n0, n1, h0, l0);
    split_pack(n2, n3, h1, l1);
    size_t o = (size_t)row * DM + 4 * t;
    *(uint2*)(yh + o) = make_uint2(h0, h1);
    *(uint2*)(yl + o) = make_uint2(l0, l1);
}

// ---------------------------------------------------------------------------
// Pure-bf16 HMMA split GEMM, cp.async double-buffered.
// A[M][K] split (Ah/Al), B[N][K] split (Bh/Bl).
// Block tile 128x128, BK=32, 8 warps (4M x 2N), warp tile 32x64.
// EPI: 1 = +bias+residual -> fp32 C
//      2 = +bias, GELU -> split bf16 (Oh/Ol, ostride)
//      3 = +bias, x0.125 on cols<1024 -> split bf16 (QKV packed, ostride)
// ---------------------------------------------------------------------------
#define OFF_AH 0u
#define OFF_AL 10240u
#define OFF_BH 20480u
#define OFF_BL 30720u
#define STAGE  40960u
#define GSMEM  (2u * STAGE)

template <int EPI>
__global__ __launch_bounds__(256, 1) void gemm_bf16(
    const bf16* __restrict__ Ah, const bf16* __restrict__ Al,
    const bf16* __restrict__ Bh, const bf16* __restrict__ Bl,
    const float* __restrict__ bias, const float* __restrict__ R,
    float* __restrict__ C, bf16* __restrict__ Oh, bf16* __restrict__ Ol,
    int ostride, int N, int K)
{
    extern __shared__ char smem[];
    const uint32_t sb = smem_u32(smem);
    const int t = threadIdx.x;
    const int lane = t & 31, w = t >> 5;
    const int wm = w & 3, wn = w >> 2;
    const int row0 = blockIdx.y * 128, col0 = blockIdx.x * 128;

    // ldsm lane offsets (stride 80B/row within each array region)
    uint32_t aOff[2];
#pragma unroll
    for (int i = 0; i < 2; i++) {
        int r = wm * 32 + i * 16 + (lane & 7) + 8 * ((lane >> 3) & 1);
        aOff[i] = (uint32_t)(r * 80 + 16 * (lane >> 4));
    }
    uint32_t bOff[4];
#pragma unroll
    for (int ng = 0; ng < 4; ng++) {
        int n = wn * 64 + ng * 16 + (lane & 7) + 8 * (lane >> 4);
        bOff[ng] = (uint32_t)(n * 80 + 16 * ((lane >> 3) & 1));
    }

    const int lr = t >> 2, lc = t & 3;     // cp.async row/col

    auto load_tile = [&](int kc, int buf) {
        const uint32_t base = sb + buf * STAGE;
        const int k0 = kc * 32;
#pragma unroll
        for (int i = 0; i < 2; i++) {
            int m = lr + 64 * i;
            uint32_t d = base + (uint32_t)(m * 80 + lc * 16);
            size_t ga = (size_t)(row0 + m) * K + k0 + lc * 8;
            size_t gb = (size_t)(col0 + m) * K + k0 + lc * 8;
            cpasync16(d + OFF_AH, Ah + ga);
            cpasync16(d + OFF_AL, Al + ga);
            cpasync16(d + OFF_BH, Bh + gb);
            cpasync16(d + OFF_BL, Bl + gb);
        }
    };

    float acc[2][8][4] = {};

    const int nk = K >> 5;
    load_tile(0, 0);
    CP_COMMIT();

    for (int kc = 0; kc < nk; kc++) {
        if (kc + 1 < nk) {
            load_tile(kc + 1, (kc + 1) & 1);
            CP_COMMIT();
            CP_WAIT(1);
        } else {
            CP_WAIT(0);
        }
        __syncthreads();

        const uint32_t bs = sb + (kc & 1) * STAGE;
#pragma unroll
        for (int ks = 0; ks < 2; ks++) {
            const uint32_t kb = ks * 32;
            uint32_t ah[2][4], al[2][4], bh[4][4], bl[4][4];
#pragma unroll
            for (int i = 0; i < 2; i++) {
                ldsm4(ah[i], bs + OFF_AH + aOff[i] + kb);
                ldsm4(al[i], bs + OFF_AL + aOff[i] + kb);
            }
#pragma unroll
            for (int ng = 0; ng < 4; ng++) {
                ldsm4(bh[ng], bs + OFF_BH + bOff[ng] + kb);
                ldsm4(bl[ng], bs + OFF_BL + bOff[ng] + kb);
            }
#pragma unroll
            for (int i = 0; i < 2; i++)
#pragma unroll
                for (int j = 0; j < 8; j++) {
                    const int jj = j >> 1, e = (j & 1) * 2;
                    mma16816(acc[i][j], ah[i], bh[jj][e], bh[jj][e + 1]);
                    mma16816(acc[i][j], ah[i], bl[jj][e], bl[jj][e + 1]);
                    mma16816(acc[i][j], al[i], bh[jj][e], bh[jj][e + 1]);
                }
        }
        __syncthreads();
    }

    // --- epilogue ---
#pragma unroll
    for (int i = 0; i < 2; i++) {
#pragma unroll
        for (int j = 0; j < 8; j++) {
            int r = row0 + wm * 32 + i * 16 + (lane >> 2);
            int cg = col0 + wn * 64 + j * 8 + 2 * (lane & 3);
#pragma unroll
            for (int half = 0; half < 2; half++) {
                int rr = r + half * 8;
                float vx = acc[i][j][half * 2 + 0] + bias[cg];
                float vy = acc[i][j][half * 2 + 1] + bias[cg + 1];
                if (EPI == 1) {
                    size_t idx = (size_t)rr * N + cg;
                    float2 r2 = *(const float2*)(R + idx);
                    *(float2*)(C + idx) = make_float2(vx + r2.x, vy + r2.y);
                } else {
                    if (EPI == 2) {
                        vx = 0.5f * vx * (1.0f + erff(vx * 0.70710678118654752f));
                        vy = 0.5f * vy * (1.0f + erff(vy * 0.70710678118654752f));
                    }
                    if (EPI == 3 && cg < 1024) { vx *= 0.125f; vy *= 0.125f; }
                    uint32_t hp, lp;
                    split_pack(vx, vy, hp, lp);
                    size_t idx = (size_t)rr * ostride + cg;
                    *(uint32_t*)(Oh + idx) = hp;
                    *(uint32_t*)(Ol + idx) = lp;
                }
            }
        }
    }
}

// ---------------------------------------------------------------------------
// HMMA flash attention over packed split-QKV (row stride 3072).
// Block = 128 q-rows x 1 head, 8 warps. kv tile 64.
// ---------------------------------------------------------------------------
#define TSTRB 144
#define AQH 0u
#define AQL (128u * TSTRB)
#define AKH (2u * 128u * TSTRB)
#define AKL (AKH + 64u * TSTRB)
#define AVH (AKH + 2u * 64u * TSTRB)
#define AVL (AKH + 3u * 64u * TSTRB)
#define ATTN_SMEM (2u * 128u * TSTRB + 4u * 64u * TSTRB)

__global__ __launch_bounds__(256, 2) void attn_bf16(
    const bf16* __restrict__ qkvh, const bf16* __restrict__ qkvl,
    bf16* __restrict__ ctxh, bf16* __restrict__ ctxl)
{
    extern __shared__ char smem[];
    const uint32_t sb = smem_u32(smem);
    const int t = threadIdx.x;
    const int lane = t & 31, w = t >> 5;
    const int h = blockIdx.y;
    const int q0 = blockIdx.x * 128;
    const int hcol = h * DHD;

    // ---- load Q tile ----
#pragma unroll
    for (int it = 0; it < 4; it++) {
        int idx = t + 256 * it;
        int r = idx >> 3, c = idx & 7;
        size_t g = (size_t)(q0 + r) * QKVN + hcol + c * 8;
        uint32_t so = (uint32_t)(r * TSTRB + c * 16);
        *(uint4*)(smem + AQH + so) = *(const uint4*)(qkvh + g);
        *(uint4*)(smem + AQL + so) = *(const uint4*)(qkvl + g);
    }

    const uint32_t aOff = (uint32_t)((w * 16 + (lane & 15)) * TSTRB + 16 * (lane >> 4));
    uint32_t bOff[4];
#pragma unroll
    for (int ng = 0; ng < 4; ng++)
        bOff[ng] = (uint32_t)((ng * 16 + (lane & 7) + 8 * (lane >> 4)) * TSTRB
                              + 16 * ((lane >> 3) & 1));
    const uint32_t vOff = (uint32_t)(((lane & 7) + 8 * ((lane >> 3) & 1)) * TSTRB
                                     + 16 * (lane >> 4));

    float of[8][4] = {};
    float m0 = -1e30f, m1 = -1e30f, l0 = 0.f, l1 = 0.f;
    __syncthreads();

    for (int kb = 0; kb < SQ / 64; kb++) {
        const int k0 = kb * 64;

#pragma unroll
        for (int it = 0; it < 2; it++) {
            int idx = t + 256 * it;
            int r = idx >> 3, c = idx & 7;
            size_t gk = (size_t)(k0 + r) * QKVN + 1024 + hcol + c * 8;
            size_t gv = gk + 1024;
            uint32_t so = (uint32_t)(r * TSTRB + c * 16);
            *(uint4*)(smem + AKH + so) = *(const uint4*)(qkvh + gk);
            *(uint4*)(smem + AKL + so) = *(const uint4*)(qkvl + gk);
            *(uint4*)(smem + AVH + so) = *(const uint4*)(qkvh + gv);
            *(uint4*)(smem + AVL + so) = *(const uint4*)(qkvl + gv);
        }
        __syncthreads();

        // ---- S = Q @ K^T (3-term split) ----
        float sa[8][4] = {};
#pragma unroll
        for (int ks = 0; ks < 4; ks++) {
            const uint32_t kbyte = ks * 32;
            uint32_t qfh[4], qfl[4];
            ldsm4(qfh, sb + AQH + aOff + kbyte);
            ldsm4(qfl, sb + AQL + aOff + kbyte);
#pragma unroll
            for (int ng = 0; ng < 4; ng++) {
                uint32_t kfh[4], kfl[4];
                ldsm4(kfh, sb + AKH + bOff[ng] + kbyte);
                ldsm4(kfl, sb + AKL + bOff[ng] + kbyte);
                mma16816(sa[2 * ng],     qfh, kfh[0], kfh[1]);
                mma16816(sa[2 * ng + 1], qfh, kfh[2], kfh[3]);
                mma16816(sa[2 * ng],     qfh, kfl[0], kfl[1]);
                mma16816(sa[2 * ng + 1], qfh, kfl[2], kfl[3]);
                mma16816(sa[2 * ng],     qfl, kfh[0], kfh[1]);
                mma16816(sa[2 * ng + 1], qfl, kfh[2], kfh[3]);
            }
        }

        // ---- online softmax ----
        float mx0 = -1e30f, mx1 = -1e30f;
#pragma unroll
        for (int nf = 0; nf < 8; nf++) {
            mx0 = fmaxf(mx0, fmaxf(sa[nf][0], sa[nf][1]));
            mx1 = fmaxf(mx1, fmaxf(sa[nf][2], sa[nf][3]));
        }
#pragma unroll
        for (int o = 1; o <= 2; o <<= 1) {
            mx0 = fmaxf(mx0, __shfl_xor_sync(0xffffffffu, mx0, o));
            mx1 = fmaxf(mx1, __shfl_xor_sync(0xffffffffu, mx1, o));
        }
        float mn0 = fmaxf(m0, mx0), mn1 = fmaxf(m1, mx1);
        float al0 = __expf(m0 - mn0), al1 = __expf(m1 - mn1);
        m0 = mn0; m1 = mn1;
        float rs0 = 0.f, rs1 = 0.f;
#pragma unroll
        for (int nf = 0; nf < 8; nf++) {
            sa[nf][0] = __expf(sa[nf][0] - mn0);
            sa[nf][1] = __expf(sa[nf][1] - mn0);
            sa[nf][2] = __expf(sa[nf][2] - mn1);
            sa[nf][3] = __expf(sa[nf][3] - mn1);
            rs0 += sa[nf][0] + sa[nf][1];
            rs1 += sa[nf][2] + sa[nf][3];
        }
#pragma unroll
        for (int o = 1; o <= 2; o <<= 1) {
            rs0 += __shfl_xor_sync(0xffffffffu, rs0, o);
            rs1 += __shfl_xor_sync(0xffffffffu, rs1, o);
        }
        l0 = l0 * al0 + rs0;
        l1 = l1 * al1 + rs1;
#pragma unroll
        for (int nf = 0; nf < 8; nf++) {
            of[nf][0] *= al0; of[nf][1] *= al0;
            of[nf][2] *= al1; of[nf][3] *= al1;
        }

        // ---- O += P @ V (2-term) ----
#pragma unroll
        for (int j = 0; j < 4; j++) {
            uint32_t pa[4];
            pa[0] = pack_bf16(sa[2 * j][0],     sa[2 * j][1]);
            pa[1] = pack_bf16(sa[2 * j][2],     sa[2 * j][3]);
            pa[2] = pack_bf16(sa[2 * j + 1][0], sa[2 * j + 1][1]);
            pa[3] = pack_bf16(sa[2 * j + 1][2], sa[2 * j + 1][3]);
            const uint32_t tOff = vOff + (uint32_t)(j * 16 * TSTRB);
#pragma unroll
            for (int g = 0; g < 4; g++) {
                uint32_t vfh[4], vfl[4];
                ldsm4t(vfh, sb + AVH + tOff + g * 32);
                ldsm4t(vfl, sb + AVL + tOff + g * 32);
                mma16816(of[2 * g],     pa, vfh[0], vfh[1]);
                mma16816(of[2 * g + 1], pa, vfh[2], vfh[3]);
                mma16816(of[2 * g],     pa, vfl[0], vfl[1]);
                mma16816(of[2 * g + 1], pa, vfl[2], vfl[3]);
            }
        }
        __syncthreads();
    }

    // ---- epilogue: normalize, write split ctx ----
    const float inv0 = 1.0f / l0, inv1 = 1.0f / l1;
    const int r0 = q0 + w * 16 + (lane >> 2);
#pragma unroll
    for (int nf = 0; nf < 8; nf++) {
        int d = nf * 8 + 2 * (lane & 3);
        uint32_t hp, lp;
        size_t i0 = (size_t)r0 * DM + hcol + d;
        size_t i1 = (size_t)(r0 + 8) * DM + hcol + d;
        split_pack(of[nf][0] * inv0, of[nf][1] * inv0, hp, lp);
        *(uint32_t*)(ctxh + i0) = hp; *(uint32_t*)(ctxl + i0) = lp;
        split_pack(of[nf][2] * inv1, of[nf][3] * inv1, hp, lp);
        *(uint32_t*)(ctxh + i1) = hp; *(uint32_t*)(ctxl + i1) = lp;
    }
}

// ---------------------------------------------------------------------------
extern "C" void kernel_launch(void* const* d_in, const int* in_sizes, int n_in,
                              void* d_out, int out_size)
{
    const float* x   = (const float*)d_in[0];
    const float* Wq  = (const float*)d_in[1];
    const float* bq  = (const float*)d_in[2];
    const float* Wk  = (const float*)d_in[3];
    const float* bk  = (const float*)d_in[4];
    const float* Wv  = (const float*)d_in[5];
    const float* bv  = (const float*)d_in[6];
    const float* Wo  = (const float*)d_in[7];
    const float* bo  = (const float*)d_in[8];
    const float* l1s = (const float*)d_in[9];
    const float* l1b = (const float*)d_in[10];
    const float* l2s = (const float*)d_in[11];
    const float* l2b = (const float*)d_in[12];
    const float* W1  = (const float*)d_in[13];
    const float* b1  = (const float*)d_in[14];
    const float* W2  = (const float*)d_in[15];
    const float* b2  = (const float*)d_in[16];
    float* out = (float*)d_out;

    bf16 *yh, *yl, *qkvh, *qkvl, *ctxh, *ctxl, *y2h, *y2l, *hh, *hl;
    bf16 *wqkvh, *wqkvl, *woh, *wol, *w1h, *w1l, *w2h, *w2l;
    float *bqkv;
    cudaGetSymbolAddress((void**)&yh, g_yh);     cudaGetSymbolAddress((void**)&yl, g_yl);
    cudaGetSymbolAddress((void**)&qkvh, g_qkvh); cudaGetSymbolAddress((void**)&qkvl, g_qkvl);
    cudaGetSymbolAddress((void**)&ctxh, g_ctxh); cudaGetSymbolAddress((void**)&ctxl, g_ctxl);
    cudaGetSymbolAddress((void**)&y2h, g_y2h);   cudaGetSymbolAddress((void**)&y2l, g_y2l);
    cudaGetSymbolAddress((void**)&hh, g_hh);     cudaGetSymbolAddress((void**)&hl, g_hl);
    cudaGetSymbolAddress((void**)&wqkvh, g_wqkvh); cudaGetSymbolAddress((void**)&wqkvl, g_wqkvl);
    cudaGetSymbolAddress((void**)&woh, g_woh);   cudaGetSymbolAddress((void**)&wol, g_wol);
    cudaGetSymbolAddress((void**)&w1h, g_w1h);   cudaGetSymbolAddress((void**)&w1l, g_w1l);
    cudaGetSymbolAddress((void**)&w2h, g_w2h);   cudaGetSymbolAddress((void**)&w2l, g_w2l);
    cudaGetSymbolAddress((void**)&bqkv, g_bqkv);

    cudaFuncSetAttribute(attn_bf16, cudaFuncAttributeMaxDynamicSharedMemorySize, ATTN_SMEM);
    cudaFuncSetAttribute(gemm_bf16<1>, cudaFuncAttributeMaxDynamicSharedMemorySize, GSMEM);
    cudaFuncSetAttribute(gemm_bf16<2>, cudaFuncAttributeMaxDynamicSharedMemorySize, GSMEM);
    cudaFuncSetAttribute(gemm_bf16<3>, cudaFuncAttributeMaxDynamicSharedMemorySize, GSMEM);

    // ---- weight prep (once per launch) ----
    pack_bias<<<12, 256>>>(bq, bk, bv, bqkv);
    wconv<<<dim3(32, 32), 256>>>(Wq, wqkvh,                wqkvl,                DM, DM);
    wconv<<<dim3(32, 32), 256>>>(Wk, wqkvh + 1024 * DM,    wqkvl + 1024 * DM,    DM, DM);
    wconv<<<dim3(32, 32), 256>>>(Wv, wqkvh + 2048 * DM,    wqkvl + 2048 * DM,    DM, DM);
    wconv<<<dim3(32, 32), 256>>>(Wo, woh, wol, DM, DM);
    wconv<<<dim3(128, 32), 256>>>(W1, w1h, w1l, DM, FF);   // [N=4096][K=1024]
    wconv<<<dim3(32, 128), 256>>>(W2, w2h, w2l, FF, DM);   // [N=1024][K=4096]

    // ---- LN1 ----
    ln_split<<<SQ, 256>>>(x, l1s, l1b, yh, yl);

    // ---- fused QKV: [4096,1024] @ [1024,3072] -> packed split qkv ----
    gemm_bf16<3><<<dim3(QKVN / 128, SQ / 128), 256, GSMEM>>>(
        yh, yl, wqkvh, wqkvl, bqkv, nullptr, nullptr, qkvh, qkvl, QKVN, QKVN, DM);

    // ---- attention ----
    attn_bf16<<<dim3(SQ / 128, NH), 256, ATTN_SMEM>>>(qkvh, qkvl, ctxh, ctxl);

    // ---- output projection + residual ----
    gemm_bf16<1><<<dim3(DM / 128, SQ / 128), 256, GSMEM>>>(
        ctxh, ctxl, woh, wol, bo, x, out, nullptr, nullptr, DM, DM, DM);

    // ---- LN2 ----
    ln_split<<<SQ, 256>>>(out, l2s, l2b, y2h, y2l);

    // ---- FFN1 + GELU -> split h ----
    gemm_bf16<2><<<dim3(FF / 128, SQ / 128), 256, GSMEM>>>(
        y2h, y2l, w1h, w1l, b1, nullptr, nullptr, hh, hl, FF, FF, DM);

    // ---- FFN2 + residual (C==R aliasing safe) ----
    gemm_bf16<1><<<dim3(DM / 128, SQ / 128), 256, GSMEM>>>(
        hh, hl, w2h, w2l, b2, out, out, nullptr, nullptr, DM, DM, FF);
}

// round 11
// speedup vs baseline: 1.0515x; 1.0515x over previous
#include <cuda_runtime.h>
#include <cuda_bf16.h>
#include <math.h>
#include <stdint.h>

#define SQ 4096
#define DM 1024
#define NH 16
#define DHD 64
#define FF 4096
#define QKVN 3072

typedef __nv_bfloat16 bf16;

// Scratch (device globals — no runtime allocation allowed)
__device__ bf16 g_yh [SQ*DM],   g_yl [SQ*DM];    // LN1 out split
__device__ bf16 g_qkvh[SQ*QKVN],g_qkvl[SQ*QKVN]; // packed q|k|v split
__device__ bf16 g_ctxh[SQ*DM],  g_ctxl[SQ*DM];   // attention out split
__device__ bf16 g_y2h[SQ*DM],   g_y2l[SQ*DM];    // LN2 out split
__device__ bf16 g_hh [SQ*FF],   g_hl [SQ*FF];    // GELU out split
// transposed split weights [N][K]
__device__ bf16 g_wqkvh[QKVN*DM], g_wqkvl[QKVN*DM];
__device__ bf16 g_woh [DM*DM],  g_wol [DM*DM];
__device__ bf16 g_w1h [FF*DM],  g_w1l [FF*DM];
__device__ bf16 g_w2h [DM*FF],  g_w2l [DM*FF];
__device__ float g_bqkv[QKVN];

// ===========================================================================
// Helpers
// ===========================================================================
__device__ __forceinline__ uint32_t smem_u32(const void* p) {
    uint32_t a;
    asm("{ .reg .u64 t; cvta.to.shared.u64 t, %1; cvt.u32.u64 %0, t; }" : "=r"(a) : "l"(p));
    return a;
}
__device__ __forceinline__ void ldsm4(uint32_t* r, uint32_t addr) {
    asm volatile("ldmatrix.sync.aligned.m8n8.x4.shared.b16 {%0,%1,%2,%3}, [%4];"
        : "=r"(r[0]), "=r"(r[1]), "=r"(r[2]), "=r"(r[3]) : "r"(addr));
}
__device__ __forceinline__ void ldsm4t(uint32_t* r, uint32_t addr) {
    asm volatile("ldmatrix.sync.aligned.m8n8.x4.trans.shared.b16 {%0,%1,%2,%3}, [%4];"
        : "=r"(r[0]), "=r"(r[1]), "=r"(r[2]), "=r"(r[3]) : "r"(addr));
}
__device__ __forceinline__ void mma16816(float* c, const uint32_t* a,
                                         uint32_t b0, uint32_t b1) {
    asm volatile("mma.sync.aligned.m16n8k16.row.col.f32.bf16.bf16.f32 "
        "{%0,%1,%2,%3}, {%4,%5,%6,%7}, {%8,%9}, {%0,%1,%2,%3};"
        : "+f"(c[0]), "+f"(c[1]), "+f"(c[2]), "+f"(c[3])
        : "r"(a[0]), "r"(a[1]), "r"(a[2]), "r"(a[3]), "r"(b0), "r"(b1));
}
__device__ __forceinline__ void cpasync16(uint32_t dst, const void* src) {
    asm volatile("cp.async.cg.shared.global [%0], [%1], 16;" :: "r"(dst), "l"(src));
}
#define CP_COMMIT() asm volatile("cp.async.commit_group;" ::: "memory")
#define CP_WAIT(n)  asm volatile("cp.async.wait_group %0;" :: "n"(n) : "memory")

__device__ __forceinline__ void split_pack(float x0, float x1, uint32_t& hp, uint32_t& lp) {
    bf16 h0 = __float2bfloat16_rn(x0);
    bf16 h1 = __float2bfloat16_rn(x1);
    bf16 l0 = __float2bfloat16_rn(x0 - __bfloat162float(h0));
    bf16 l1 = __float2bfloat16_rn(x1 - __bfloat162float(h1));
    hp = (uint32_t)__bfloat16_as_ushort(h0) | ((uint32_t)__bfloat16_as_ushort(h1) << 16);
    lp = (uint32_t)__bfloat16_as_ushort(l0) | ((uint32_t)__bfloat16_as_ushort(l1) << 16);
}
__device__ __forceinline__ uint32_t pack_bf16(float x0, float x1) {
    __nv_bfloat162 p = __floats2bfloat162_rn(x0, x1);
    return *(uint32_t*)&p;
}

// ---------------------------------------------------------------------------
// Weight transpose + split: W[K][N] fp32 -> Th/Tl[N][K] bf16
// ---------------------------------------------------------------------------
__global__ __launch_bounds__(256) void wconv(const float* __restrict__ W,
                                             bf16* __restrict__ Th,
                                             bf16* __restrict__ Tl,
                                             int K, int N)
{
    __shared__ float tile[32][33];
    const int n0 = blockIdx.x * 32, k0 = blockIdx.y * 32;
    const int t = threadIdx.x;
#pragma unroll
    for (int i = 0; i < 4; i++) {
        int idx = t + 256 * i;
        int kr = idx >> 5, nc = idx & 31;
        tile[kr][nc] = W[(size_t)(k0 + kr) * N + n0 + nc];
    }
    __syncthreads();
#pragma unroll
    for (int i = 0; i < 2; i++) {
        int idx = t + 256 * i;
        int n = idx >> 4, c = idx & 15;
        uint32_t hp, lp;
        split_pack(tile[2 * c][n], tile[2 * c + 1][n], hp, lp);
        size_t o = (size_t)(n0 + n) * K + k0 + 2 * c;
        *(uint32_t*)(Th + o) = hp;
        *(uint32_t*)(Tl + o) = lp;
    }
}

__global__ void pack_bias(const float* __restrict__ bq, const float* __restrict__ bk,
                          const float* __restrict__ bv, float* __restrict__ dst)
{
    int i = blockIdx.x * 256 + threadIdx.x;
    if (i < 1024) dst[i] = bq[i];
    else if (i < 2048) dst[i] = bk[i - 1024];
    else if (i < QKVN) dst[i] = bv[i - 2048];
}

// ---------------------------------------------------------------------------
// LayerNorm -> split bf16. One block/row, 256 threads.
// ---------------------------------------------------------------------------
__global__ __launch_bounds__(256) void ln_split(const float* __restrict__ x,
                                                const float* __restrict__ sc,
                                                const float* __restrict__ bi,
                                                bf16* __restrict__ yh,
                                                bf16* __restrict__ yl)
{
    int row = blockIdx.x;
    const float* xr = x + (size_t)row * DM;
    int t = threadIdx.x;

    float4 v = *(const float4*)(xr + 4 * t);
    float s = v.x + v.y + v.z + v.w;

    __shared__ float red[8];
#pragma unroll
    for (int o = 16; o > 0; o >>= 1) s += __shfl_xor_sync(0xffffffffu, s, o);
    if ((t & 31) == 0) red[t >> 5] = s;
    __syncthreads();
    if (t < 32) {
        float r = (t < 8) ? red[t] : 0.f;
#pragma unroll
        for (int o = 4; o > 0; o >>= 1) r += __shfl_xor_sync(0xffffffffu, r, o);
        if (t == 0) red[0] = r;
    }
    __syncthreads();
    float mu = red[0] * (1.0f / DM);
    __syncthreads();

    float d0 = v.x - mu, d1 = v.y - mu, d2 = v.z - mu, d3 = v.w - mu;
    float vs = d0 * d0 + d1 * d1 + d2 * d2 + d3 * d3;
#pragma unroll
    for (int o = 16; o > 0; o >>= 1) vs += __shfl_xor_sync(0xffffffffu, vs, o);
    if ((t & 31) == 0) red[t >> 5] = vs;
    __syncthreads();
    if (t < 32) {
        float r = (t < 8) ? red[t] : 0.f;
#pragma unroll
        for (int o = 4; o > 0; o >>= 1) r += __shfl_xor_sync(0xffffffffu, r, o);
        if (t == 0) red[0] = r;
    }
    __syncthreads();
    float rstd = rsqrtf(red[0] * (1.0f / DM) + 1e-6f);

    float4 s4 = *(const float4*)(sc + 4 * t);
    float4 b4 = *(const float4*)(bi + 4 * t);
    float n0 = d0 * rstd * s4.x + b4.x;
    float n1 = d1 * rstd * s4.y + b4.y;
    float n2 = d2 * rstd * s4.z + b4.z;
    float n3 = d3 * rstd * s4.w + b4.w;
    uint32_t h0, l0, h1, l1;
    split_pack(n0, n1, h0, l0);
    split_pack(n2, n3, h1, l1);
    size_t o = (size_t)row * DM + 4 * t;
    *(uint2*)(yh + o) = make_uint2(h0, h1);
    *(uint2*)(yl + o) = make_uint2(l0, l1);
}

// ---------------------------------------------------------------------------
// Pure-bf16 HMMA split GEMM, cp.async 3-stage pipelined.
// A[M][K] split (Ah/Al), B[N][K] split (Bh/Bl).
// Block tile 128x128, BK=32, 512 threads = 16 warps (4M x 4N), warp tile 32x32.
// EPI: 1 = +bias+residual -> fp32 C
//      2 = +bias, GELU -> split bf16 (Oh/Ol, ostride)
//      3 = +bias, x0.125 on cols<1024 -> split bf16 (QKV packed, ostride)
// ---------------------------------------------------------------------------
#define OFF_AH 0u
#define OFF_AL 10240u
#define OFF_BH 20480u
#define OFF_BL 30720u
#define STAGE  40960u
#define GSMEM  (3u * STAGE)

template <int EPI>
__global__ __launch_bounds__(512, 1) void gemm_bf16(
    const bf16* __restrict__ Ah, const bf16* __restrict__ Al,
    const bf16* __restrict__ Bh, const bf16* __restrict__ Bl,
    const float* __restrict__ bias, const float* __restrict__ R,
    float* __restrict__ C, bf16* __restrict__ Oh, bf16* __restrict__ Ol,
    int ostride, int N, int K)
{
    extern __shared__ char smem[];
    const uint32_t sb = smem_u32(smem);
    const int t = threadIdx.x;
    const int lane = t & 31, w = t >> 5;
    const int wm = w & 3, wn = w >> 2;          // 4x4 warp grid
    const int row0 = blockIdx.y * 128, col0 = blockIdx.x * 128;

    // ldsm lane offsets (stride 80B/row within each array region)
    uint32_t aOff[2];
#pragma unroll
    for (int i = 0; i < 2; i++) {
        int r = wm * 32 + i * 16 + (lane & 7) + 8 * ((lane >> 3) & 1);
        aOff[i] = (uint32_t)(r * 80 + 16 * (lane >> 4));
    }
    uint32_t bOff[2];
#pragma unroll
    for (int jj = 0; jj < 2; jj++) {
        int n = wn * 32 + jj * 16 + (lane & 7) + 8 * (lane >> 4);
        bOff[jj] = (uint32_t)(n * 80 + 16 * ((lane >> 3) & 1));
    }

    const int lr = t >> 2, lc = t & 3;          // 512 threads: row 0..127, chunk 0..3

    auto load_tile = [&](int kc, int buf) {
        const uint32_t base = sb + (uint32_t)buf * STAGE;
        const int k0 = kc * 32;
        uint32_t d = base + (uint32_t)(lr * 80 + lc * 16);
        size_t ga = (size_t)(row0 + lr) * K + k0 + lc * 8;
        size_t gb = (size_t)(col0 + lr) * K + k0 + lc * 8;
        cpasync16(d + OFF_AH, Ah + ga);
        cpasync16(d + OFF_AL, Al + ga);
        cpasync16(d + OFF_BH, Bh + gb);
        cpasync16(d + OFF_BL, Bl + gb);
    };

    float acc[2][4][4] = {};

    const int nk = K >> 5;
    load_tile(0, 0); CP_COMMIT();
    load_tile(1, 1); CP_COMMIT();

    int buf = 0;
    for (int kc = 0; kc < nk; kc++) {
        CP_WAIT(1);                 // stage for kc is complete
        __syncthreads();            // all warps done computing stage (kc-1)%3 == (kc+2)%3

        if (kc + 2 < nk) {          // prefetch into the stage freed last iteration
            int nb = buf + 2; if (nb >= 3) nb -= 3;
            load_tile(kc + 2, nb);
            CP_COMMIT();
        }

        const uint32_t bs = sb + (uint32_t)buf * STAGE;
#pragma unroll
        for (int ks = 0; ks < 2; ks++) {
            const uint32_t kb = ks * 32;
            uint32_t ah[2][4], al[2][4], bh[2][4], bl[2][4];
#pragma unroll
            for (int i = 0; i < 2; i++) {
                ldsm4(ah[i], bs + OFF_AH + aOff[i] + kb);
                ldsm4(al[i], bs + OFF_AL + aOff[i] + kb);
            }
#pragma unroll
            for (int jj = 0; jj < 2; jj++) {
                ldsm4(bh[jj], bs + OFF_BH + bOff[jj] + kb);
                ldsm4(bl[jj], bs + OFF_BL + bOff[jj] + kb);
            }
#pragma unroll
            for (int i = 0; i < 2; i++)
#pragma unroll
                for (int j = 0; j < 4; j++) {
                    const int jj = j >> 1, e = (j & 1) * 2;
                    mma16816(acc[i][j], ah[i], bh[jj][e], bh[jj][e + 1]);
                    mma16816(acc[i][j], ah[i], bl[jj][e], bl[jj][e + 1]);
                    mma16816(acc[i][j], al[i], bh[jj][e], bh[jj][e + 1]);
                }
        }
        if (++buf >= 3) buf -= 3;
    }

    // --- epilogue ---
#pragma unroll
    for (int i = 0; i < 2; i++) {
#pragma unroll
        for (int j = 0; j < 4; j++) {
            int r = row0 + wm * 32 + i * 16 + (lane >> 2);
            int cg = col0 + wn * 32 + j * 8 + 2 * (lane & 3);
#pragma unroll
            for (int half = 0; half < 2; half++) {
                int rr = r + half * 8;
                float vx = acc[i][j][half * 2 + 0] + bias[cg];
                float vy = acc[i][j][half * 2 + 1] + bias[cg + 1];
                if (EPI == 1) {
                    size_t idx = (size_t)rr * N + cg;
                    float2 r2 = *(const float2*)(R + idx);
                    *(float2*)(C + idx) = make_float2(vx + r2.x, vy + r2.y);
                } else {
                    if (EPI == 2) {
                        vx = 0.5f * vx * (1.0f + erff(vx * 0.70710678118654752f));
                        vy = 0.5f * vy * (1.0f + erff(vy * 0.70710678118654752f));
                    }
                    if (EPI == 3 && cg < 1024) { vx *= 0.125f; vy *= 0.125f; }
                    uint32_t hp, lp;
                    split_pack(vx, vy, hp, lp);
                    size_t idx = (size_t)rr * ostride + cg;
                    *(uint32_t*)(Oh + idx) = hp;
                    *(uint32_t*)(Ol + idx) = lp;
                }
            }
        }
    }
}

// ---------------------------------------------------------------------------
// HMMA flash attention over packed split-QKV (row stride 3072).
// Block = 128 q-rows x 1 head, 8 warps. kv tile 64.
// ---------------------------------------------------------------------------
#define TSTRB 144
#define AQH 0u
#define AQL (128u * TSTRB)
#define AKH (2u * 128u * TSTRB)
#define AKL (AKH + 64u * TSTRB)
#define AVH (AKH + 2u * 64u * TSTRB)
#define AVL (AKH + 3u * 64u * TSTRB)
#define ATTN_SMEM (2u * 128u * TSTRB + 4u * 64u * TSTRB)

__global__ __launch_bounds__(256, 2) void attn_bf16(
    const bf16* __restrict__ qkvh, const bf16* __restrict__ qkvl,
    bf16* __restrict__ ctxh, bf16* __restrict__ ctxl)
{
    extern __shared__ char smem[];
    const uint32_t sb = smem_u32(smem);
    const int t = threadIdx.x;
    const int lane = t & 31, w = t >> 5;
    const int h = blockIdx.y;
    const int q0 = blockIdx.x * 128;
    const int hcol = h * DHD;

    // ---- load Q tile ----
#pragma unroll
    for (int it = 0; it < 4; it++) {
        int idx = t + 256 * it;
        int r = idx >> 3, c = idx & 7;
        size_t g = (size_t)(q0 + r) * QKVN + hcol + c * 8;
        uint32_t so = (uint32_t)(r * TSTRB + c * 16);
        *(uint4*)(smem + AQH + so) = *(const uint4*)(qkvh + g);
        *(uint4*)(smem + AQL + so) = *(const uint4*)(qkvl + g);
    }

    const uint32_t aOff = (uint32_t)((w * 16 + (lane & 15)) * TSTRB + 16 * (lane >> 4));
    uint32_t bOff[4];
#pragma unroll
    for (int ng = 0; ng < 4; ng++)
        bOff[ng] = (uint32_t)((ng * 16 + (lane & 7) + 8 * (lane >> 4)) * TSTRB
                              + 16 * ((lane >> 3) & 1));
    const uint32_t vOff = (uint32_t)(((lane & 7) + 8 * ((lane >> 3) & 1)) * TSTRB
                                     + 16 * (lane >> 4));

    float of[8][4] = {};
    float m0 = -1e30f, m1 = -1e30f, l0 = 0.f, l1 = 0.f;
    __syncthreads();

    for (int kb = 0; kb < SQ / 64; kb++) {
        const int k0 = kb * 64;

#pragma unroll
        for (int it = 0; it < 2; it++) {
            int idx = t + 256 * it;
            int r = idx >> 3, c = idx & 7;
            size_t gk = (size_t)(k0 + r) * QKVN + 1024 + hcol + c * 8;
            size_t gv = gk + 1024;
            uint32_t so = (uint32_t)(r * TSTRB + c * 16);
            *(uint4*)(smem + AKH + so) = *(const uint4*)(qkvh + gk);
            *(uint4*)(smem + AKL + so) = *(const uint4*)(qkvl + gk);
            *(uint4*)(smem + AVH + so) = *(const uint4*)(qkvh + gv);
            *(uint4*)(smem + AVL + so) = *(const uint4*)(qkvl + gv);
        }
        __syncthreads();

        // ---- S = Q @ K^T (3-term split) ----
        float sa[8][4] = {};
#pragma unroll
        for (int ks = 0; ks < 4; ks++) {
            const uint32_t kbyte = ks * 32;
            uint32_t qfh[4], qfl[4];
            ldsm4(qfh, sb + AQH + aOff + kbyte);
            ldsm4(qfl, sb + AQL + aOff + kbyte);
#pragma unroll
            for (int ng = 0; ng < 4; ng++) {
                uint32_t kfh[4], kfl[4];
                ldsm4(kfh, sb + AKH + bOff[ng] + kbyte);
                ldsm4(kfl, sb + AKL + bOff[ng] + kbyte);
                mma16816(sa[2 * ng],     qfh, kfh[0], kfh[1]);
                mma16816(sa[2 * ng + 1], qfh, kfh[2], kfh[3]);
                mma16816(sa[2 * ng],     qfh, kfl[0], kfl[1]);
                mma16816(sa[2 * ng + 1], qfh, kfl[2], kfl[3]);
                mma16816(sa[2 * ng],     qfl, kfh[0], kfh[1]);
                mma16816(sa[2 * ng + 1], qfl, kfh[2], kfh[3]);
            }
        }

        // ---- online softmax ----
        float mx0 = -1e30f, mx1 = -1e30f;
#pragma unroll
        for (int nf = 0; nf < 8; nf++) {
            mx0 = fmaxf(mx0, fmaxf(sa[nf][0], sa[nf][1]));
            mx1 = fmaxf(mx1, fmaxf(sa[nf][2], sa[nf][3]));
        }
#pragma unroll
        for (int o = 1; o <= 2; o <<= 1) {
            mx0 = fmaxf(mx0, __shfl_xor_sync(0xffffffffu, mx0, o));
            mx1 = fmaxf(mx1, __shfl_xor_sync(0xffffffffu, mx1, o));
        }
        float mn0 = fmaxf(m0, mx0), mn1 = fmaxf(m1, mx1);
        float al0 = __expf(m0 - mn0), al1 = __expf(m1 - mn1);
        m0 = mn0; m1 = mn1;
        float rs0 = 0.f, rs1 = 0.f;
#pragma unroll
        for (int nf = 0; nf < 8; nf++) {
            sa[nf][0] = __expf(sa[nf][0] - mn0);
            sa[nf][1] = __expf(sa[nf][1] - mn0);
            sa[nf][2] = __expf(sa[nf][2] - mn1);
            sa[nf][3] = __expf(sa[nf][3] - mn1);
            rs0 += sa[nf][0] + sa[nf][1];
            rs1 += sa[nf][2] + sa[nf][3];
        }
#pragma unroll
        for (int o = 1; o <= 2; o <<= 1) {
            rs0 += __shfl_xor_sync(0xffffffffu, rs0, o);
            rs1 += __shfl_xor_sync(0xffffffffu, rs1, o);
        }
        l0 = l0 * al0 + rs0;
        l1 = l1 * al1 + rs1;
#pragma unroll
        for (int nf = 0; nf < 8; nf++) {
            of[nf][0] *= al0; of[nf][1] *= al0;
            of[nf][2] *= al1; of[nf][3] *= al1;
        }

        // ---- O += P @ V (2-term) ----
#pragma unroll
        for (int j = 0; j < 4; j++) {
            uint32_t pa[4];
            pa[0] = pack_bf16(sa[2 * j][0],     sa[2 * j][1]);
            pa[1] = pack_bf16(sa[2 * j][2],     sa[2 * j][3]);
            pa[2] = pack_bf16(sa[2 * j + 1][0], sa[2 * j + 1][1]);
            pa[3] = pack_bf16(sa[2 * j + 1][2], sa[2 * j + 1][3]);
            const uint32_t tOff = vOff + (uint32_t)(j * 16 * TSTRB);
#pragma unroll
            for (int g = 0; g < 4; g++) {
                uint32_t vfh[4], vfl[4];
                ldsm4t(vfh, sb + AVH + tOff + g * 32);
                ldsm4t(vfl, sb + AVL + tOff + g * 32);
                mma16816(of[2 * g],     pa, vfh[0], vfh[1]);
                mma16816(of[2 * g + 1], pa, vfh[2], vfh[3]);
                mma16816(of[2 * g],     pa, vfl[0], vfl[1]);
                mma16816(of[2 * g + 1], pa, vfl[2], vfl[3]);
            }
        }
        __syncthreads();
    }

    // ---- epilogue: normalize, write split ctx ----
    const float inv0 = 1.0f / l0, inv1 = 1.0f / l1;
    const int r0 = q0 + w * 16 + (lane >> 2);
#pragma unroll
    for (int nf = 0; nf < 8; nf++) {
        int d = nf * 8 + 2 * (lane & 3);
        uint32_t hp, lp;
        size_t i0 = (size_t)r0 * DM + hcol + d;
        size_t i1 = (size_t)(r0 + 8) * DM + hcol + d;
        split_pack(of[nf][0] * inv0, of[nf][1] * inv0, hp, lp);
        *(uint32_t*)(ctxh + i0) = hp; *(uint32_t*)(ctxl + i0) = lp;
        split_pack(of[nf][2] * inv1, of[nf][3] * inv1, hp, lp);
        *(uint32_t*)(ctxh + i1) = hp; *(uint32_t*)(ctxl + i1) = lp;
    }
}

// ---------------------------------------------------------------------------
extern "C" void kernel_launch(void* const* d_in, const int* in_sizes, int n_in,
                              void* d_out, int out_size)
{
    const float* x   = (const float*)d_in[0];
    const float* Wq  = (const float*)d_in[1];
    const float* bq  = (const float*)d_in[2];
    const float* Wk  = (const float*)d_in[3];
    const float* bk  = (const float*)d_in[4];
    const float* Wv  = (const float*)d_in[5];
    const float* bv  = (const float*)d_in[6];
    const float* Wo  = (const float*)d_in[7];
    const float* bo  = (const float*)d_in[8];
    const float* l1s = (const float*)d_in[9];
    const float* l1b = (const float*)d_in[10];
    const float* l2s = (const float*)d_in[11];
    const float* l2b = (const float*)d_in[12];
    const float* W1  = (const float*)d_in[13];
    const float* b1  = (const float*)d_in[14];
    const float* W2  = (const float*)d_in[15];
    const float* b2  = (const float*)d_in[16];
    float* out = (float*)d_out;

    bf16 *yh, *yl, *qkvh, *qkvl, *ctxh, *ctxl, *y2h, *y2l, *hh, *hl;
    bf16 *wqkvh, *wqkvl, *woh, *wol, *w1h, *w1l, *w2h, *w2l;
    float *bqkv;
    cudaGetSymbolAddress((void**)&yh, g_yh);     cudaGetSymbolAddress((void**)&yl, g_yl);
    cudaGetSymbolAddress((void**)&qkvh, g_qkvh); cudaGetSymbolAddress((void**)&qkvl, g_qkvl);
    cudaGetSymbolAddress((void**)&ctxh, g_ctxh); cudaGetSymbolAddress((void**)&ctxl, g_ctxl);
    cudaGetSymbolAddress((void**)&y2h, g_y2h);   cudaGetSymbolAddress((void**)&y2l, g_y2l);
    cudaGetSymbolAddress((void**)&hh, g_hh);     cudaGetSymbolAddress((void**)&hl, g_hl);
    cudaGetSymbolAddress((void**)&wqkvh, g_wqkvh); cudaGetSymbolAddress((void**)&wqkvl, g_wqkvl);
    cudaGetSymbolAddress((void**)&woh, g_woh);   cudaGetSymbolAddress((void**)&wol, g_wol);
    cudaGetSymbolAddress((void**)&w1h, g_w1h);   cudaGetSymbolAddress((void**)&w1l, g_w1l);
    cudaGetSymbolAddress((void**)&w2h, g_w2h);   cudaGetSymbolAddress((void**)&w2l, g_w2l);
    cudaGetSymbolAddress((void**)&bqkv, g_bqkv);

    cudaFuncSetAttribute(attn_bf16, cudaFuncAttributeMaxDynamicSharedMemorySize, ATTN_SMEM);
    cudaFuncSetAttribute(gemm_bf16<1>, cudaFuncAttributeMaxDynamicSharedMemorySize, GSMEM);
    cudaFuncSetAttribute(gemm_bf16<2>, cudaFuncAttributeMaxDynamicSharedMemorySize, GSMEM);
    cudaFuncSetAttribute(gemm_bf16<3>, cudaFuncAttributeMaxDynamicSharedMemorySize, GSMEM);

    // ---- weight prep (once per launch) ----
    pack_bias<<<12, 256>>>(bq, bk, bv, bqkv);
    wconv<<<dim3(32, 32), 256>>>(Wq, wqkvh,                wqkvl,                DM, DM);
    wconv<<<dim3(32, 32), 256>>>(Wk, wqkvh + 1024 * DM,    wqkvl + 1024 * DM,    DM, DM);
    wconv<<<dim3(32, 32), 256>>>(Wv, wqkvh + 2048 * DM,    wqkvl + 2048 * DM,    DM, DM);
    wconv<<<dim3(32, 32), 256>>>(Wo, woh, wol, DM, DM);
    wconv<<<dim3(128, 32), 256>>>(W1, w1h, w1l, DM, FF);   // [N=4096][K=1024]
    wconv<<<dim3(32, 128), 256>>>(W2, w2h, w2l, FF, DM);   // [N=1024][K=4096]

    // ---- LN1 ----
    ln_split<<<SQ, 256>>>(x, l1s, l1b, yh, yl);

    // ---- fused QKV: [4096,1024] @ [1024,3072] -> packed split qkv ----
    gemm_bf16<3><<<dim3(QKVN / 128, SQ / 128), 512, GSMEM>>>(
        yh, yl, wqkvh, wqkvl, bqkv, nullptr, nullptr, qkvh, qkvl, QKVN, QKVN, DM);

    // ---- attention ----
    attn_bf16<<<dim3(SQ / 128, NH), 256, ATTN_SMEM>>>(qkvh, qkvl, ctxh, ctxl);

    // ---- output projection + residual ----
    gemm_bf16<1><<<dim3(DM / 128, SQ / 128), 512, GSMEM>>>(
        ctxh, ctxl, woh, wol, bo, x, out, nullptr, nullptr, DM, DM, DM);

    // ---- LN2 ----
    ln_split<<<SQ, 256>>>(out, l2s, l2b, y2h, y2l);

    // ---- FFN1 + GELU -> split h ----
    gemm_bf16<2><<<dim3(FF / 128, SQ / 128), 512, GSMEM>>>(
        y2h, y2l, w1h, w1l, b1, nullptr, nullptr, hh, hl, FF, FF, DM);

    // ---- FFN2 + residual (C==R aliasing safe) ----
    gemm_bf16<1><<<dim3(DM / 128, SQ / 128), 512, GSMEM>>>(
        hh, hl, w2h, w2l, b2, out, out, nullptr, nullptr, DM, DM, FF);
}

// round 14
// speedup vs baseline: 1.2471x; 1.1861x over previous
#include <cuda_runtime.h>
#include <cuda_bf16.h>
#include <math.h>
#include <stdint.h>

#define SQ 4096
#define DM 1024
#define NH 16
#define DHD 64
#define FF 4096
#define QKVN 3072

typedef __nv_bfloat16 bf16;

// Scratch (device globals — no runtime allocation allowed)
__device__ float g_y  [SQ*DM];                    // LN1 out (tf32-rounded fp32)
__device__ bf16  g_qkvh[SQ*QKVN], g_qkvl[SQ*QKVN];// packed q|k|v split bf16 (attn input)
__device__ float g_ctx[SQ*DM];                    // attention out (tf32 fp32)
__device__ float g_y2 [SQ*DM];                    // LN2 out (tf32 fp32)
__device__ float g_h  [SQ*FF];                    // GELU out (tf32 fp32)
// transposed tf32 weights [N][K]
__device__ float g_wqkv[QKVN*DM];
__device__ float g_wo [DM*DM];
__device__ float g_w1 [FF*DM];
__device__ float g_w2 [DM*FF];
__device__ float g_bqkv[QKVN];

// ===========================================================================
// Helpers
// ===========================================================================
__device__ __forceinline__ uint32_t smem_u32(const void* p) {
    uint32_t a;
    asm("{ .reg .u64 t; cvta.to.shared.u64 t, %1; cvt.u32.u64 %0, t; }" : "=r"(a) : "l"(p));
    return a;
}
__device__ __forceinline__ void ldsm4(uint32_t* r, uint32_t addr) {
    asm volatile("ldmatrix.sync.aligned.m8n8.x4.shared.b16 {%0,%1,%2,%3}, [%4];"
        : "=r"(r[0]), "=r"(r[1]), "=r"(r[2]), "=r"(r[3]) : "r"(addr));
}
__device__ __forceinline__ void ldsm4t(uint32_t* r, uint32_t addr) {
    asm volatile("ldmatrix.sync.aligned.m8n8.x4.trans.shared.b16 {%0,%1,%2,%3}, [%4];"
        : "=r"(r[0]), "=r"(r[1]), "=r"(r[2]), "=r"(r[3]) : "r"(addr));
}
__device__ __forceinline__ void mma16816(float* c, const uint32_t* a,
                                         uint32_t b0, uint32_t b1) {
    asm volatile("mma.sync.aligned.m16n8k16.row.col.f32.bf16.bf16.f32 "
        "{%0,%1,%2,%3}, {%4,%5,%6,%7}, {%8,%9}, {%0,%1,%2,%3};"
        : "+f"(c[0]), "+f"(c[1]), "+f"(c[2]), "+f"(c[3])
        : "r"(a[0]), "r"(a[1]), "r"(a[2]), "r"(a[3]), "r"(b0), "r"(b1));
}
__device__ __forceinline__ void mma_tf32(float* c, const uint32_t* a,
                                         uint32_t b0, uint32_t b1) {
    asm volatile("mma.sync.aligned.m16n8k8.row.col.f32.tf32.tf32.f32 "
        "{%0,%1,%2,%3}, {%4,%5,%6,%7}, {%8,%9}, {%0,%1,%2,%3};"
        : "+f"(c[0]), "+f"(c[1]), "+f"(c[2]), "+f"(c[3])
        : "r"(a[0]), "r"(a[1]), "r"(a[2]), "r"(a[3]), "r"(b0), "r"(b1));
}
__device__ __forceinline__ float tf32r(float x) {
    float y;
    asm("cvt.rna.tf32.f32 %0, %1;" : "=f"(y) : "f"(x));
    return y;
}
__device__ __forceinline__ void cpasync16(uint32_t dst, const void* src) {
    asm volatile("cp.async.cg.shared.global [%0], [%1], 16;" :: "r"(dst), "l"(src));
}
#define CP_COMMIT() asm volatile("cp.async.commit_group;" ::: "memory")
#define CP_WAIT(n)  asm volatile("cp.async.wait_group %0;" :: "n"(n) : "memory")

__device__ __forceinline__ void split_pack(float x0, float x1, uint32_t& hp, uint32_t& lp) {
    bf16 h0 = __float2bfloat16_rn(x0);
    bf16 h1 = __float2bfloat16_rn(x1);
    bf16 l0 = __float2bfloat16_rn(x0 - __bfloat162float(h0));
    bf16 l1 = __float2bfloat16_rn(x1 - __bfloat162float(h1));
    hp = (uint32_t)__bfloat16_as_ushort(h0) | ((uint32_t)__bfloat16_as_ushort(h1) << 16);
    lp = (uint32_t)__bfloat16_as_ushort(l0) | ((uint32_t)__bfloat16_as_ushort(l1) << 16);
}
__device__ __forceinline__ uint32_t pack_bf16(float x0, float x1) {
    __nv_bfloat162 p = __floats2bfloat162_rn(x0, x1);
    return *(uint32_t*)&p;
}

// ---------------------------------------------------------------------------
// Weight transpose (+tf32 round): W[K][N] fp32 -> T[N][K] fp32
// ---------------------------------------------------------------------------
__global__ __launch_bounds__(256) void wconv_t(const float* __restrict__ W,
                                               float* __restrict__ T,
                                               int K, int N)
{
    __shared__ float tile[32][33];
    const int n0 = blockIdx.x * 32, k0 = blockIdx.y * 32;
    const int t = threadIdx.x;
#pragma unroll
    for (int i = 0; i < 4; i++) {
        int idx = t + 256 * i;
        int kr = idx >> 5, nc = idx & 31;
        tile[kr][nc] = W[(size_t)(k0 + kr) * N + n0 + nc];
    }
    __syncthreads();
#pragma unroll
    for (int i = 0; i < 4; i++) {
        int idx = t + 256 * i;
        int n = idx >> 5, kk = idx & 31;
        T[(size_t)(n0 + n) * K + k0 + kk] = tf32r(tile[kk][n]);
    }
}

__global__ void pack_bias(const float* __restrict__ bq, const float* __restrict__ bk,
                          const float* __restrict__ bv, float* __restrict__ dst)
{
    int i = blockIdx.x * 256 + threadIdx.x;
    if (i < 1024) dst[i] = bq[i];
    else if (i < 2048) dst[i] = bk[i - 1024];
    else if (i < QKVN) dst[i] = bv[i - 2048];
}

// ---------------------------------------------------------------------------
// LayerNorm -> tf32-rounded fp32. One block/row, 256 threads.
// ---------------------------------------------------------------------------
__global__ __launch_bounds__(256) void ln_tf32(const float* __restrict__ x,
                                               const float* __restrict__ sc,
                                               const float* __restrict__ bi,
                                               float* __restrict__ y)
{
    int row = blockIdx.x;
    const float* xr = x + (size_t)row * DM;
    int t = threadIdx.x;

    float4 v = *(const float4*)(xr + 4 * t);
    float s = v.x + v.y + v.z + v.w;

    __shared__ float red[8];
#pragma unroll
    for (int o = 16; o > 0; o >>= 1) s += __shfl_xor_sync(0xffffffffu, s, o);
    if ((t & 31) == 0) red[t >> 5] = s;
    __syncthreads();
    if (t < 32) {
        float r = (t < 8) ? red[t] : 0.f;
#pragma unroll
        for (int o = 4; o > 0; o >>= 1) r += __shfl_xor_sync(0xffffffffu, r, o);
        if (t == 0) red[0] = r;
    }
    __syncthreads();
    float mu = red[0] * (1.0f / DM);
    __syncthreads();

    float d0 = v.x - mu, d1 = v.y - mu, d2 = v.z - mu, d3 = v.w - mu;
    float vs = d0 * d0 + d1 * d1 + d2 * d2 + d3 * d3;
#pragma unroll
    for (int o = 16; o > 0; o >>= 1) vs += __shfl_xor_sync(0xffffffffu, vs, o);
    if ((t & 31) == 0) red[t >> 5] = vs;
    __syncthreads();
    if (t < 32) {
        float r = (t < 8) ? red[t] : 0.f;
#pragma unroll
        for (int o = 4; o > 0; o >>= 1) r += __shfl_xor_sync(0xffffffffu, r, o);
        if (t == 0) red[0] = r;
    }
    __syncthreads();
    float rstd = rsqrtf(red[0] * (1.0f / DM) + 1e-6f);

    float4 s4 = *(const float4*)(sc + 4 * t);
    float4 b4 = *(const float4*)(bi + 4 * t);
    float4 o4;
    o4.x = tf32r(d0 * rstd * s4.x + b4.x);
    o4.y = tf32r(d1 * rstd * s4.y + b4.y);
    o4.z = tf32r(d2 * rstd * s4.z + b4.z);
    o4.w = tf32r(d3 * rstd * s4.w + b4.w);
    *(float4*)(y + (size_t)row * DM + 4 * t) = o4;
}

// ---------------------------------------------------------------------------
// TF32 HMMA GEMM, cp.async 3-stage pipelined.
// A[M][K] fp32 (tf32-rounded), B[N][K] fp32 (tf32-rounded).
// Block tile 128x128, BK=32, 512 threads = 16 warps (4M x 4N), warp tile 32x32.
// smem rows: 32 floats (128B) + 16B pad = 144B stride (conflict-free ldsm).
// EPI: 1 = +bias+residual -> fp32 C
//      2 = +bias, GELU -> tf32 fp32 O
//      3 = +bias, x0.125 on cols<1024 -> split bf16 (QKV packed, ostride)
// ---------------------------------------------------------------------------
#define GROWB 144u
#define GS_B  18432u            // 128 rows * 144B
#define GSTAGE 36864u
#define GSMEM  (3u * GSTAGE)    // 110592

template <int EPI>
__global__ __launch_bounds__(512, 1) void gemm_tf32(
    const float* __restrict__ A, const float* __restrict__ B,
    const float* __restrict__ bias, const float* __restrict__ R,
    float* __restrict__ C, float* __restrict__ O,
    bf16* __restrict__ Oh, bf16* __restrict__ Ol,
    int ostride, int N, int K)
{
    extern __shared__ char smem[];
    const uint32_t sb = smem_u32(smem);
    const int t = threadIdx.x;
    const int lane = t & 31, w = t >> 5;
    const int wm = w & 3, wn = w >> 2;          // 4x4 warp grid
    const int row0 = blockIdx.y * 128, col0 = blockIdx.x * 128;

    // ldsm lane offsets: tiles {r0-7,c0-3},{r8-15,c0-3},{r0-7,c4-7},{r8-15,c4-7}
    uint32_t aOff[2];
#pragma unroll
    for (int i = 0; i < 2; i++) {
        int r = wm * 32 + i * 16 + (lane & 7) + 8 * ((lane >> 3) & 1);
        aOff[i] = (uint32_t)(r * GROWB + 16 * (lane >> 4));
    }
    uint32_t bOff[2];
#pragma unroll
    for (int jj = 0; jj < 2; jj++) {
        int n = wn * 32 + jj * 16 + (lane & 7) + 8 * ((lane >> 3) & 1);
        bOff[jj] = (uint32_t)(n * GROWB + 16 * (lane >> 4));
    }

    auto load_tile = [&](int kc, int buf) {
        const uint32_t base = sb + (uint32_t)buf * GSTAGE;
        const int k0 = kc * 32;
#pragma unroll
        for (int i = 0; i < 2; i++) {
            int id = t + 512 * i;                 // 1024 16B-chunks per array
            int r = id >> 3, ch = id & 7;
            uint32_t d = base + (uint32_t)(r * GROWB + ch * 16);
            cpasync16(d,        A + (size_t)(row0 + r) * K + k0 + ch * 4);
            cpasync16(d + GS_B, B + (size_t)(col0 + r) * K + k0 + ch * 4);
        }
    };

    float acc[2][4][4] = {};

    const int nk = K >> 5;
    load_tile(0, 0); CP_COMMIT();
    load_tile(1, 1); CP_COMMIT();

    int buf = 0;
    for (int kc = 0; kc < nk; kc++) {
        CP_WAIT(1);
        __syncthreads();

        if (kc + 2 < nk) {
            int nb = buf + 2; if (nb >= 3) nb -= 3;
            load_tile(kc + 2, nb);
            CP_COMMIT();
        }

        const uint32_t bs = sb + (uint32_t)buf * GSTAGE;
#pragma unroll
        for (int ks = 0; ks < 4; ks++) {          // k8 steps within BK=32
            const uint32_t kb = ks * 32;          // 8 floats = 32B
            uint32_t af[2][4], bfr[2][4];
#pragma unroll
            for (int i = 0; i < 2; i++)
                ldsm4(af[i], bs + aOff[i] + kb);
#pragma unroll
            for (int jj = 0; jj < 2; jj++)
                ldsm4(bfr[jj], bs + GS_B + bOff[jj] + kb);
            // b-frag mapping: group (2*jj+s): b0=bfr[jj][s], b1=bfr[jj][s+2]
#pragma unroll
            for (int i = 0; i < 2; i++)
#pragma unroll
                for (int j = 0; j < 4; j++) {
                    const int jj = j >> 1, s = j & 1;
                    mma_tf32(acc[i][j], af[i], bfr[jj][s], bfr[jj][s + 2]);
                }
        }
        if (++buf >= 3) buf -= 3;
    }

    // --- epilogue ---
#pragma unroll
    for (int i = 0; i < 2; i++) {
#pragma unroll
        for (int j = 0; j < 4; j++) {
            int r = row0 + wm * 32 + i * 16 + (lane >> 2);
            int cg = col0 + wn * 32 + j * 8 + 2 * (lane & 3);
#pragma unroll
            for (int half = 0; half < 2; half++) {
                int rr = r + half * 8;
                float vx = acc[i][j][half * 2 + 0] + bias[cg];
                float vy = acc[i][j][half * 2 + 1] + bias[cg + 1];
                if (EPI == 1) {
                    size_t idx = (size_t)rr * N + cg;
                    float2 r2 = *(const float2*)(R + idx);
                    *(float2*)(C + idx) = make_float2(vx + r2.x, vy + r2.y);
                } else if (EPI == 2) {
                    vx = 0.5f * vx * (1.0f + erff(vx * 0.70710678118654752f));
                    vy = 0.5f * vy * (1.0f + erff(vy * 0.70710678118654752f));
                    size_t idx = (size_t)rr * ostride + cg;
                    *(float2*)(O + idx) = make_float2(tf32r(vx), tf32r(vy));
                } else {
                    if (cg < 1024) { vx *= 0.125f; vy *= 0.125f; }
                    uint32_t hp, lp;
                    split_pack(vx, vy, hp, lp);
                    size_t idx = (size_t)rr * ostride + cg;
                    *(uint32_t*)(Oh + idx) = hp;
                    *(uint32_t*)(Ol + idx) = lp;
                }
            }
        }
    }
}

// ---------------------------------------------------------------------------
// HMMA flash attention over packed split-QKV (row stride 3072).
// Block = 128 q-rows x 1 head, 8 warps. kv tile 64. Output: tf32 fp32 ctx.
// ---------------------------------------------------------------------------
#define TSTRB 144
#define AQH 0u
#define AQL (128u * TSTRB)
#define AKH (2u * 128u * TSTRB)
#define AKL (AKH + 64u * TSTRB)
#define AVH (AKH + 2u * 64u * TSTRB)
#define AVL (AKH + 3u * 64u * TSTRB)
#define ATTN_SMEM (2u * 128u * TSTRB + 4u * 64u * TSTRB)

__global__ __launch_bounds__(256, 2) void attn_bf16(
    const bf16* __restrict__ qkvh, const bf16* __restrict__ qkvl,
    float* __restrict__ ctx)
{
    extern __shared__ char smem[];
    const uint32_t sb = smem_u32(smem);
    const int t = threadIdx.x;
    const int lane = t & 31, w = t >> 5;
    const int h = blockIdx.y;
    const int q0 = blockIdx.x * 128;
    const int hcol = h * DHD;

    // ---- load Q tile ----
#pragma unroll
    for (int it = 0; it < 4; it++) {
        int idx = t + 256 * it;
        int r = idx >> 3, c = idx & 7;
        size_t g = (size_t)(q0 + r) * QKVN + hcol + c * 8;
        uint32_t so = (uint32_t)(r * TSTRB + c * 16);
        *(uint4*)(smem + AQH + so) = *(const uint4*)(qkvh + g);
        *(uint4*)(smem + AQL + so) = *(const uint4*)(qkvl + g);
    }

    const uint32_t aOff = (uint32_t)((w * 16 + (lane & 15)) * TSTRB + 16 * (lane >> 4));
    uint32_t bOff[4];
#pragma unroll
    for (int ng = 0; ng < 4; ng++)
        bOff[ng] = (uint32_t)((ng * 16 + (lane & 7) + 8 * (lane >> 4)) * TSTRB
                              + 16 * ((lane >> 3) & 1));
    const uint32_t vOff = (uint32_t)(((lane & 7) + 8 * ((lane >> 3) & 1)) * TSTRB
                                     + 16 * (lane >> 4));

    float of[8][4] = {};
    float m0 = -1e30f, m1 = -1e30f, l0 = 0.f, l1 = 0.f;
    __syncthreads();

    for (int kb = 0; kb < SQ / 64; kb++) {
        const int k0 = kb * 64;

#pragma unroll
        for (int it = 0; it < 2; it++) {
            int idx = t + 256 * it;
            int r = idx >> 3, c = idx & 7;
            size_t gk = (size_t)(k0 + r) * QKVN + 1024 + hcol + c * 8;
            size_t gv = gk + 1024;
            uint32_t so = (uint32_t)(r * TSTRB + c * 16);
            *(uint4*)(smem + AKH + so) = *(const uint4*)(qkvh + gk);
            *(uint4*)(smem + AKL + so) = *(const uint4*)(qkvl + gk);
            *(uint4*)(smem + AVH + so) = *(const uint4*)(qkvh + gv);
            *(uint4*)(smem + AVL + so) = *(const uint4*)(qkvl + gv);
        }
        __syncthreads();

        // ---- S = Q @ K^T (3-term split) ----
        float sa[8][4] = {};
#pragma unroll
        for (int ks = 0; ks < 4; ks++) {
            const uint32_t kbyte = ks * 32;
            uint32_t qfh[4], qfl[4];
            ldsm4(qfh, sb + AQH + aOff + kbyte);
            ldsm4(qfl, sb + AQL + aOff + kbyte);
#pragma unroll
            for (int ng = 0; ng < 4; ng++) {
                uint32_t kfh[4], kfl[4];
                ldsm4(kfh, sb + AKH + bOff[ng] + kbyte);
                ldsm4(kfl, sb + AKL + bOff[ng] + kbyte);
                mma16816(sa[2 * ng],     qfh, kfh[0], kfh[1]);
                mma16816(sa[2 * ng + 1], qfh, kfh[2], kfh[3]);
                mma16816(sa[2 * ng],     qfh, kfl[0], kfl[1]);
                mma16816(sa[2 * ng + 1], qfh, kfl[2], kfl[3]);
                mma16816(sa[2 * ng],     qfl, kfh[0], kfh[1]);
                mma16816(sa[2 * ng + 1], qfl, kfh[2], kfh[3]);
            }
        }

        // ---- online softmax ----
        float mx0 = -1e30f, mx1 = -1e30f;
#pragma unroll
        for (int nf = 0; nf < 8; nf++) {
            mx0 = fmaxf(mx0, fmaxf(sa[nf][0], sa[nf][1]));
            mx1 = fmaxf(mx1, fmaxf(sa[nf][2], sa[nf][3]));
        }
#pragma unroll
        for (int o = 1; o <= 2; o <<= 1) {
            mx0 = fmaxf(mx0, __shfl_xor_sync(0xffffffffu, mx0, o));
            mx1 = fmaxf(mx1, __shfl_xor_sync(0xffffffffu, mx1, o));
        }
        float mn0 = fmaxf(m0, mx0), mn1 = fmaxf(m1, mx1);
        float al0 = __expf(m0 - mn0), al1 = __expf(m1 - mn1);
        m0 = mn0; m1 = mn1;
        float rs0 = 0.f, rs1 = 0.f;
#pragma unroll
        for (int nf = 0; nf < 8; nf++) {
            sa[nf][0] = __expf(sa[nf][0] - mn0);
            sa[nf][1] = __expf(sa[nf][1] - mn0);
            sa[nf][2] = __expf(sa[nf][2] - mn1);
            sa[nf][3] = __expf(sa[nf][3] - mn1);
            rs0 += sa[nf][0] + sa[nf][1];
            rs1 += sa[nf][2] + sa[nf][3];
        }
#pragma unroll
        for (int o = 1; o <= 2; o <<= 1) {
            rs0 += __shfl_xor_sync(0xffffffffu, rs0, o);
            rs1 += __shfl_xor_sync(0xffffffffu, rs1, o);
        }
        l0 = l0 * al0 + rs0;
        l1 = l1 * al1 + rs1;
#pragma unroll
        for (int nf = 0; nf < 8; nf++) {
            of[nf][0] *= al0; of[nf][1] *= al0;
            of[nf][2] *= al1; of[nf][3] *= al1;
        }

        // ---- O += P @ V (2-term) ----
#pragma unroll
        for (int j = 0; j < 4; j++) {
            uint32_t pa[4];
            pa[0] = pack_bf16(sa[2 * j][0],     sa[2 * j][1]);
            pa[1] = pack_bf16(sa[2 * j][2],     sa[2 * j][3]);
            pa[2] = pack_bf16(sa[2 * j + 1][0], sa[2 * j + 1][1]);
            pa[3] = pack_bf16(sa[2 * j + 1][2], sa[2 * j + 1][3]);
            const uint32_t tOff = vOff + (uint32_t)(j * 16 * TSTRB);
#pragma unroll
            for (int g = 0; g < 4; g++) {
                uint32_t vfh[4], vfl[4];
                ldsm4t(vfh, sb + AVH + tOff + g * 32);
                ldsm4t(vfl, sb + AVL + tOff + g * 32);
                mma16816(of[2 * g],     pa, vfh[0], vfh[1]);
                mma16816(of[2 * g + 1], pa, vfh[2], vfh[3]);
                mma16816(of[2 * g],     pa, vfl[0], vfl[1]);
                mma16816(of[2 * g + 1], pa, vfl[2], vfl[3]);
            }
        }
        __syncthreads();
    }

    // ---- epilogue: normalize, write tf32 fp32 ctx ----
    const float inv0 = 1.0f / l0, inv1 = 1.0f / l1;
    const int r0 = q0 + w * 16 + (lane >> 2);
#pragma unroll
    for (int nf = 0; nf < 8; nf++) {
        int d = nf * 8 + 2 * (lane & 3);
        size_t i0 = (size_t)r0 * DM + hcol + d;
        size_t i1 = (size_t)(r0 + 8) * DM + hcol + d;
        *(float2*)(ctx + i0) = make_float2(tf32r(of[nf][0] * inv0), tf32r(of[nf][1] * inv0));
        *(float2*)(ctx + i1) = make_float2(tf32r(of[nf][2] * inv1), tf32r(of[nf][3] * inv1));
    }
}

// ---------------------------------------------------------------------------
extern "C" void kernel_launch(void* const* d_in, const int* in_sizes, int n_in,
                              void* d_out, int out_size)
{
    const float* x   = (const float*)d_in[0];
    const float* Wq  = (const float*)d_in[1];
    const float* bq  = (const float*)d_in[2];
    const float* Wk  = (const float*)d_in[3];
    const float* bk  = (const float*)d_in[4];
    const float* Wv  = (const float*)d_in[5];
    const float* bv  = (const float*)d_in[6];
    const float* Wo  = (const float*)d_in[7];
    const float* bo  = (const float*)d_in[8];
    const float* l1s = (const float*)d_in[9];
    const float* l1b = (const float*)d_in[10];
    const float* l2s = (const float*)d_in[11];
    const float* l2b = (const float*)d_in[12];
    const float* W1  = (const float*)d_in[13];
    const float* b1  = (const float*)d_in[14];
    const float* W2  = (const float*)d_in[15];
    const float* b2  = (const float*)d_in[16];
    float* out = (float*)d_out;

    float *y, *ctx, *y2, *hbuf, *wqkv, *wo, *w1, *w2, *bqkv;
    bf16 *qkvh, *qkvl;
    cudaGetSymbolAddress((void**)&y, g_y);
    cudaGetSymbolAddress((void**)&qkvh, g_qkvh); cudaGetSymbolAddress((void**)&qkvl, g_qkvl);
    cudaGetSymbolAddress((void**)&ctx, g_ctx);
    cudaGetSymbolAddress((void**)&y2, g_y2);
    cudaGetSymbolAddress((void**)&hbuf, g_h);
    cudaGetSymbolAddress((void**)&wqkv, g_wqkv);
    cudaGetSymbolAddress((void**)&wo, g_wo);
    cudaGetSymbolAddress((void**)&w1, g_w1);
    cudaGetSymbolAddress((void**)&w2, g_w2);
    cudaGetSymbolAddress((void**)&bqkv, g_bqkv);

    cudaFuncSetAttribute(attn_bf16, cudaFuncAttributeMaxDynamicSharedMemorySize, ATTN_SMEM);
    cudaFuncSetAttribute(gemm_tf32<1>, cudaFuncAttributeMaxDynamicSharedMemorySize, GSMEM);
    cudaFuncSetAttribute(gemm_tf32<2>, cudaFuncAttributeMaxDynamicSharedMemorySize, GSMEM);
    cudaFuncSetAttribute(gemm_tf32<3>, cudaFuncAttributeMaxDynamicSharedMemorySize, GSMEM);

    // ---- weight prep (once per launch) ----
    pack_bias<<<12, 256>>>(bq, bk, bv, bqkv);
    wconv_t<<<dim3(32, 32), 256>>>(Wq, wqkv,             DM, DM);
    wconv_t<<<dim3(32, 32), 256>>>(Wk, wqkv + 1024 * DM, DM, DM);
    wconv_t<<<dim3(32, 32), 256>>>(Wv, wqkv + 2048 * DM, DM, DM);
    wconv_t<<<dim3(32, 32), 256>>>(Wo, wo, DM, DM);
    wconv_t<<<dim3(128, 32), 256>>>(W1, w1, DM, FF);   // [N=4096][K=1024]
    wconv_t<<<dim3(32, 128), 256>>>(W2, w2, FF, DM);   // [N=1024][K=4096]

    // ---- LN1 ----
    ln_tf32<<<SQ, 256>>>(x, l1s, l1b, y);

    // ---- fused QKV: tf32 GEMM -> packed split-bf16 qkv ----
    gemm_tf32<3><<<dim3(QKVN / 128, SQ / 128), 512, GSMEM>>>(
        y, wqkv, bqkv, nullptr, nullptr, nullptr, qkvh, qkvl, QKVN, QKVN, DM);

    // ---- attention (bf16-split HMMA) ----
    attn_bf16<<<dim3(SQ / 128, NH), 256, ATTN_SMEM>>>(qkvh, qkvl, ctx);

    // ---- output projection + residual ----
    gemm_tf32<1><<<dim3(DM / 128, SQ / 128), 512, GSMEM>>>(
        ctx, wo, bo, x, out, nullptr, nullptr, nullptr, DM, DM, DM);

    // ---- LN2 ----
    ln_tf32<<<SQ, 256>>>(out, l2s, l2b, y2);

    // ---- FFN1 + GELU -> tf32 fp32 h ----
    gemm_tf32<2><<<dim3(FF / 128, SQ / 128), 512, GSMEM>>>(
        y2, w1, b1, nullptr, nullptr, hbuf, nullptr, nullptr, FF, FF, DM);

    // ---- FFN2 + residual (C==R aliasing safe) ----
    gemm_tf32<1><<<dim3(DM / 128, SQ / 128), 512, GSMEM>>>(
        hbuf, w2, b2, out, out, nullptr, nullptr, nullptr, DM, DM, FF);
}

// round 15
// speedup vs baseline: 1.2706x; 1.0189x over previous
#include <cuda_runtime.h>
#include <cuda_bf16.h>
#include <math.h>
#include <stdint.h>

#define SQ 4096
#define DM 1024
#define NH 16
#define DHD 64
#define FF 4096
#define QKVN 3072

typedef __nv_bfloat16 bf16;

// Scratch (device globals — no runtime allocation allowed)
__device__ float g_y  [SQ*DM];                    // LN1 out (tf32 fp32)
__device__ float g_qk [SQ*2048];                  // packed q|k (tf32 fp32, q pre-scaled)
__device__ bf16  g_vh [SQ*DM], g_vl [SQ*DM];      // v split bf16
__device__ float g_ctx[SQ*DM];                    // attention out (tf32 fp32)
__device__ float g_y2 [SQ*DM];                    // LN2 out (tf32 fp32)
__device__ float g_h  [SQ*FF];                    // GELU out (tf32 fp32)
// transposed tf32 weights [N][K]
__device__ float g_wqkv[QKVN*DM];
__device__ float g_wo [DM*DM];
__device__ float g_w1 [FF*DM];
__device__ float g_w2 [DM*FF];
__device__ float g_bqkv[QKVN];

// ===========================================================================
// Helpers
// ===========================================================================
__device__ __forceinline__ uint32_t smem_u32(const void* p) {
    uint32_t a;
    asm("{ .reg .u64 t; cvta.to.shared.u64 t, %1; cvt.u32.u64 %0, t; }" : "=r"(a) : "l"(p));
    return a;
}
__device__ __forceinline__ void ldsm4(uint32_t* r, uint32_t addr) {
    asm volatile("ldmatrix.sync.aligned.m8n8.x4.shared.b16 {%0,%1,%2,%3}, [%4];"
        : "=r"(r[0]), "=r"(r[1]), "=r"(r[2]), "=r"(r[3]) : "r"(addr));
}
__device__ __forceinline__ void ldsm4t(uint32_t* r, uint32_t addr) {
    asm volatile("ldmatrix.sync.aligned.m8n8.x4.trans.shared.b16 {%0,%1,%2,%3}, [%4];"
        : "=r"(r[0]), "=r"(r[1]), "=r"(r[2]), "=r"(r[3]) : "r"(addr));
}
__device__ __forceinline__ void mma16816(float* c, const uint32_t* a,
                                         uint32_t b0, uint32_t b1) {
    asm volatile("mma.sync.aligned.m16n8k16.row.col.f32.bf16.bf16.f32 "
        "{%0,%1,%2,%3}, {%4,%5,%6,%7}, {%8,%9}, {%0,%1,%2,%3};"
        : "+f"(c[0]), "+f"(c[1]), "+f"(c[2]), "+f"(c[3])
        : "r"(a[0]), "r"(a[1]), "r"(a[2]), "r"(a[3]), "r"(b0), "r"(b1));
}
__device__ __forceinline__ void mma_tf32(float* c, const uint32_t* a,
                                         uint32_t b0, uint32_t b1) {
    asm volatile("mma.sync.aligned.m16n8k8.row.col.f32.tf32.tf32.f32 "
        "{%0,%1,%2,%3}, {%4,%5,%6,%7}, {%8,%9}, {%0,%1,%2,%3};"
        : "+f"(c[0]), "+f"(c[1]), "+f"(c[2]), "+f"(c[3])
        : "r"(a[0]), "r"(a[1]), "r"(a[2]), "r"(a[3]), "r"(b0), "r"(b1));
}
__device__ __forceinline__ float tf32r(float x) {
    float y;
    asm("cvt.rna.tf32.f32 %0, %1;" : "=f"(y) : "f"(x));
    return y;
}
__device__ __forceinline__ void cpasync16(uint32_t dst, const void* src) {
    asm volatile("cp.async.cg.shared.global [%0], [%1], 16;" :: "r"(dst), "l"(src));
}
#define CP_COMMIT() asm volatile("cp.async.commit_group;" ::: "memory")
#define CP_WAIT(n)  asm volatile("cp.async.wait_group %0;" :: "n"(n) : "memory")

__device__ __forceinline__ void split_pack(float x0, float x1, uint32_t& hp, uint32_t& lp) {
    bf16 h0 = __float2bfloat16_rn(x0);
    bf16 h1 = __float2bfloat16_rn(x1);
    bf16 l0 = __float2bfloat16_rn(x0 - __bfloat162float(h0));
    bf16 l1 = __float2bfloat16_rn(x1 - __bfloat162float(h1));
    hp = (uint32_t)__bfloat16_as_ushort(h0) | ((uint32_t)__bfloat16_as_ushort(h1) << 16);
    lp = (uint32_t)__bfloat16_as_ushort(l0) | ((uint32_t)__bfloat16_as_ushort(l1) << 16);
}
__device__ __forceinline__ uint32_t pack_bf16(float x0, float x1) {
    __nv_bfloat162 p = __floats2bfloat162_rn(x0, x1);
    return *(uint32_t*)&p;
}

// ---------------------------------------------------------------------------
// Weight transpose (+tf32 round): W[K][N] fp32 -> T[N][K] fp32
// ---------------------------------------------------------------------------
__global__ __launch_bounds__(256) void wconv_t(const float* __restrict__ W,
                                               float* __restrict__ T,
                                               int K, int N)
{
    __shared__ float tile[32][33];
    const int n0 = blockIdx.x * 32, k0 = blockIdx.y * 32;
    const int t = threadIdx.x;
#pragma unroll
    for (int i = 0; i < 4; i++) {
        int idx = t + 256 * i;
        int kr = idx >> 5, nc = idx & 31;
        tile[kr][nc] = W[(size_t)(k0 + kr) * N + n0 + nc];
    }
    __syncthreads();
#pragma unroll
    for (int i = 0; i < 4; i++) {
        int idx = t + 256 * i;
        int n = idx >> 5, kk = idx & 31;
        T[(size_t)(n0 + n) * K + k0 + kk] = tf32r(tile[kk][n]);
    }
}

__global__ void pack_bias(const float* __restrict__ bq, const float* __restrict__ bk,
                          const float* __restrict__ bv, float* __restrict__ dst)
{
    int i = blockIdx.x * 256 + threadIdx.x;
    if (i < 1024) dst[i] = bq[i];
    else if (i < 2048) dst[i] = bk[i - 1024];
    else if (i < QKVN) dst[i] = bv[i - 2048];
}

// ---------------------------------------------------------------------------
// LayerNorm -> tf32-rounded fp32. One block/row, 256 threads.
// ---------------------------------------------------------------------------
__global__ __launch_bounds__(256) void ln_tf32(const float* __restrict__ x,
                                               const float* __restrict__ sc,
                                               const float* __restrict__ bi,
                                               float* __restrict__ y)
{
    int row = blockIdx.x;
    const float* xr = x + (size_t)row * DM;
    int t = threadIdx.x;

    float4 v = *(const float4*)(xr + 4 * t);
    float s = v.x + v.y + v.z + v.w;

    __shared__ float red[8];
#pragma unroll
    for (int o = 16; o > 0; o >>= 1) s += __shfl_xor_sync(0xffffffffu, s, o);
    if ((t & 31) == 0) red[t >> 5] = s;
    __syncthreads();
    if (t < 32) {
        float r = (t < 8) ? red[t] : 0.f;
#pragma unroll
        for (int o = 4; o > 0; o >>= 1) r += __shfl_xor_sync(0xffffffffu, r, o);
        if (t == 0) red[0] = r;
    }
    __syncthreads();
    float mu = red[0] * (1.0f / DM);
    __syncthreads();

    float d0 = v.x - mu, d1 = v.y - mu, d2 = v.z - mu, d3 = v.w - mu;
    float vs = d0 * d0 + d1 * d1 + d2 * d2 + d3 * d3;
#pragma unroll
    for (int o = 16; o > 0; o >>= 1) vs += __shfl_xor_sync(0xffffffffu, vs, o);
    if ((t & 31) == 0) red[t >> 5] = vs;
    __syncthreads();
    if (t < 32) {
        float r = (t < 8) ? red[t] : 0.f;
#pragma unroll
        for (int o = 4; o > 0; o >>= 1) r += __shfl_xor_sync(0xffffffffu, r, o);
        if (t == 0) red[0] = r;
    }
    __syncthreads();
    float rstd = rsqrtf(red[0] * (1.0f / DM) + 1e-6f);

    float4 s4 = *(const float4*)(sc + 4 * t);
    float4 b4 = *(const float4*)(bi + 4 * t);
    float4 o4;
    o4.x = tf32r(d0 * rstd * s4.x + b4.x);
    o4.y = tf32r(d1 * rstd * s4.y + b4.y);
    o4.z = tf32r(d2 * rstd * s4.z + b4.z);
    o4.w = tf32r(d3 * rstd * s4.w + b4.w);
    *(float4*)(y + (size_t)row * DM + 4 * t) = o4;
}

// ---------------------------------------------------------------------------
// TF32 HMMA GEMM, cp.async 3-stage pipelined. (proven R14 config)
// EPI: 1 = +bias+residual -> fp32 C
//      2 = +bias, GELU -> tf32 fp32 O
//      3 = QKV: cols<1024 x0.125; cols<2048 -> tf32 fp32 QK buffer (stride 2048)
//               cols>=2048 -> split bf16 V (Oh/Ol, stride 1024)
// ---------------------------------------------------------------------------
#define GROWB 144u
#define GS_B  18432u            // 128 rows * 144B
#define GSTAGE 36864u
#define GSMEM  (3u * GSTAGE)    // 110592

template <int EPI>
__global__ __launch_bounds__(512, 1) void gemm_tf32(
    const float* __restrict__ A, const float* __restrict__ B,
    const float* __restrict__ bias, const float* __restrict__ R,
    float* __restrict__ C, float* __restrict__ O,
    bf16* __restrict__ Oh, bf16* __restrict__ Ol,
    int ostride, int N, int K)
{
    extern __shared__ char smem[];
    const uint32_t sb = smem_u32(smem);
    const int t = threadIdx.x;
    const int lane = t & 31, w = t >> 5;
    const int wm = w & 3, wn = w >> 2;
    const int row0 = blockIdx.y * 128, col0 = blockIdx.x * 128;

    uint32_t aOff[2];
#pragma unroll
    for (int i = 0; i < 2; i++) {
        int r = wm * 32 + i * 16 + (lane & 7) + 8 * ((lane >> 3) & 1);
        aOff[i] = (uint32_t)(r * GROWB + 16 * (lane >> 4));
    }
    uint32_t bOff[2];
#pragma unroll
    for (int jj = 0; jj < 2; jj++) {
        int n = wn * 32 + jj * 16 + (lane & 7) + 8 * ((lane >> 3) & 1);
        bOff[jj] = (uint32_t)(n * GROWB + 16 * (lane >> 4));
    }

    auto load_tile = [&](int kc, int buf) {
        const uint32_t base = sb + (uint32_t)buf * GSTAGE;
        const int k0 = kc * 32;
#pragma unroll
        for (int i = 0; i < 2; i++) {
            int id = t + 512 * i;
            int r = id >> 3, ch = id & 7;
            uint32_t d = base + (uint32_t)(r * GROWB + ch * 16);
            cpasync16(d,        A + (size_t)(row0 + r) * K + k0 + ch * 4);
            cpasync16(d + GS_B, B + (size_t)(col0 + r) * K + k0 + ch * 4);
        }
    };

    float acc[2][4][4] = {};

    const int nk = K >> 5;
    load_tile(0, 0); CP_COMMIT();
    load_tile(1, 1); CP_COMMIT();

    int buf = 0;
    for (int kc = 0; kc < nk; kc++) {
        CP_WAIT(1);
        __syncthreads();

        if (kc + 2 < nk) {
            int nb = buf + 2; if (nb >= 3) nb -= 3;
            load_tile(kc + 2, nb);
            CP_COMMIT();
        }

        const uint32_t bs = sb + (uint32_t)buf * GSTAGE;
#pragma unroll
        for (int ks = 0; ks < 4; ks++) {
            const uint32_t kb = ks * 32;
            uint32_t af[2][4], bfr[2][4];
#pragma unroll
            for (int i = 0; i < 2; i++)
                ldsm4(af[i], bs + aOff[i] + kb);
#pragma unroll
            for (int jj = 0; jj < 2; jj++)
                ldsm4(bfr[jj], bs + GS_B + bOff[jj] + kb);
#pragma unroll
            for (int i = 0; i < 2; i++)
#pragma unroll
                for (int j = 0; j < 4; j++) {
                    const int jj = j >> 1, s = j & 1;
                    mma_tf32(acc[i][j], af[i], bfr[jj][s], bfr[jj][s + 2]);
                }
        }
        if (++buf >= 3) buf -= 3;
    }

    // --- epilogue ---
#pragma unroll
    for (int i = 0; i < 2; i++) {
#pragma unroll
        for (int j = 0; j < 4; j++) {
            int r = row0 + wm * 32 + i * 16 + (lane >> 2);
            int cg = col0 + wn * 32 + j * 8 + 2 * (lane & 3);
#pragma unroll
            for (int half = 0; half < 2; half++) {
                int rr = r + half * 8;
                float vx = acc[i][j][half * 2 + 0] + bias[cg];
                float vy = acc[i][j][half * 2 + 1] + bias[cg + 1];
                if (EPI == 1) {
                    size_t idx = (size_t)rr * N + cg;
                    float2 r2 = *(const float2*)(R + idx);
                    *(float2*)(C + idx) = make_float2(vx + r2.x, vy + r2.y);
                } else if (EPI == 2) {
                    vx = 0.5f * vx * (1.0f + erff(vx * 0.70710678118654752f));
                    vy = 0.5f * vy * (1.0f + erff(vy * 0.70710678118654752f));
                    size_t idx = (size_t)rr * ostride + cg;
                    *(float2*)(O + idx) = make_float2(tf32r(vx), tf32r(vy));
                } else {
                    if (cg < 2048) {
                        if (cg < 1024) { vx *= 0.125f; vy *= 0.125f; }
                        size_t idx = (size_t)rr * 2048 + cg;
                        *(float2*)(O + idx) = make_float2(tf32r(vx), tf32r(vy));
                    } else {
                        uint32_t hp, lp;
                        split_pack(vx, vy, hp, lp);
                        size_t idx = (size_t)rr * 1024 + (cg - 2048);
                        *(uint32_t*)(Oh + idx) = hp;
                        *(uint32_t*)(Ol + idx) = lp;
                    }
                }
            }
        }
    }
}

// ---------------------------------------------------------------------------
// Mixed flash attention: S = tf32 (Q,K fp32), PV = bf16 2-term split.
// Block = 128 q-rows x 1 head, 8 warps. kv tile 64.
// Q/K smem row: 64 floats (256B) + 16B pad = 272B stride (conflict-free ldsm).
// ---------------------------------------------------------------------------
#define QROWB 272u
#define VROWB 144u
#define AQ  0u
#define AK  34816u                  // 128*272
#define AV_H 52224u                 // AK + 64*272
#define AV_L 61440u                 // + 64*144
#define ATTN_SMEM 70656u            // + 64*144

__global__ __launch_bounds__(256, 2) void attn_mix(
    const float* __restrict__ qk,
    const bf16* __restrict__ vh, const bf16* __restrict__ vl,
    float* __restrict__ ctx)
{
    extern __shared__ char smem[];
    const uint32_t sb = smem_u32(smem);
    const int t = threadIdx.x;
    const int lane = t & 31, w = t >> 5;
    const int h = blockIdx.y;
    const int q0 = blockIdx.x * 128;
    const int hcol = h * DHD;

    // ---- load Q tile (128 x 64 fp32) ----
#pragma unroll
    for (int it = 0; it < 8; it++) {
        int idx = t + 256 * it;
        int r = idx >> 4, c = idx & 15;
        *(uint4*)(smem + AQ + r * QROWB + c * 16) =
            *(const uint4*)(qk + (size_t)(q0 + r) * 2048 + hcol + c * 4);
    }

    // tf32 ldsm lane offsets (same pattern as gemm_tf32)
    const uint32_t aOffQ = (uint32_t)((w * 16 + (lane & 7) + 8 * ((lane >> 3) & 1)) * QROWB
                                      + 16 * (lane >> 4));
    uint32_t bOffK[4];
#pragma unroll
    for (int ng = 0; ng < 4; ng++)
        bOffK[ng] = (uint32_t)((ng * 16 + (lane & 7) + 8 * ((lane >> 3) & 1)) * QROWB
                               + 16 * (lane >> 4));
    const uint32_t vOff = (uint32_t)(((lane & 7) + 8 * ((lane >> 3) & 1)) * VROWB
                                     + 16 * (lane >> 4));

    float of[8][4] = {};
    float m0 = -1e30f, m1 = -1e30f, l0 = 0.f, l1 = 0.f;
    __syncthreads();

    for (int kb = 0; kb < SQ / 64; kb++) {
        const int k0 = kb * 64;

        // ---- load K (fp32 64x64) + V hi/lo (bf16 64x64) ----
#pragma unroll
        for (int it = 0; it < 4; it++) {
            int idx = t + 256 * it;
            int r = idx >> 4, c = idx & 15;
            *(uint4*)(smem + AK + r * QROWB + c * 16) =
                *(const uint4*)(qk + (size_t)(k0 + r) * 2048 + 1024 + hcol + c * 4);
        }
#pragma unroll
        for (int it = 0; it < 2; it++) {
            int idx = t + 256 * it;
            int r = idx >> 3, c = idx & 7;
            uint32_t so = (uint32_t)(r * VROWB + c * 16);
            size_t g = (size_t)(k0 + r) * 1024 + hcol + c * 8;
            *(uint4*)(smem + AV_H + so) = *(const uint4*)(vh + g);
            *(uint4*)(smem + AV_L + so) = *(const uint4*)(vl + g);
        }
        __syncthreads();

        // ---- S = Q @ K^T (tf32, 8 k8-steps) ----
        float sa[8][4] = {};
#pragma unroll
        for (int ks = 0; ks < 8; ks++) {
            const uint32_t kbyte = ks * 32;
            uint32_t af[4];
            ldsm4(af, sb + AQ + aOffQ + kbyte);
#pragma unroll
            for (int ng = 0; ng < 4; ng++) {
                uint32_t bfr[4];
                ldsm4(bfr, sb + AK + bOffK[ng] + kbyte);
                mma_tf32(sa[2 * ng],     af, bfr[0], bfr[2]);
                mma_tf32(sa[2 * ng + 1], af, bfr[1], bfr[3]);
            }
        }

        // ---- online softmax ----
        float mx0 = -1e30f, mx1 = -1e30f;
#pragma unroll
        for (int nf = 0; nf < 8; nf++) {
            mx0 = fmaxf(mx0, fmaxf(sa[nf][0], sa[nf][1]));
            mx1 = fmaxf(mx1, fmaxf(sa[nf][2], sa[nf][3]));
        }
#pragma unroll
        for (int o = 1; o <= 2; o <<= 1) {
            mx0 = fmaxf(mx0, __shfl_xor_sync(0xffffffffu, mx0, o));
            mx1 = fmaxf(mx1, __shfl_xor_sync(0xffffffffu, mx1, o));
        }
        float mn0 = fmaxf(m0, mx0), mn1 = fmaxf(m1, mx1);
        float al0 = __expf(m0 - mn0), al1 = __expf(m1 - mn1);
        m0 = mn0; m1 = mn1;
        float rs0 = 0.f, rs1 = 0.f;
#pragma unroll
        for (int nf = 0; nf < 8; nf++) {
            sa[nf][0] = __expf(sa[nf][0] - mn0);
            sa[nf][1] = __expf(sa[nf][1] - mn0);
            sa[nf][2] = __expf(sa[nf][2] - mn1);
            sa[nf][3] = __expf(sa[nf][3] - mn1);
            rs0 += sa[nf][0] + sa[nf][1];
            rs1 += sa[nf][2] + sa[nf][3];
        }
#pragma unroll
        for (int o = 1; o <= 2; o <<= 1) {
            rs0 += __shfl_xor_sync(0xffffffffu, rs0, o);
            rs1 += __shfl_xor_sync(0xffffffffu, rs1, o);
        }
        l0 = l0 * al0 + rs0;
        l1 = l1 * al1 + rs1;
#pragma unroll
        for (int nf = 0; nf < 8; nf++) {
            of[nf][0] *= al0; of[nf][1] *= al0;
            of[nf][2] *= al1; of[nf][3] *= al1;
        }

        // ---- O += P @ V (bf16 2-term) ----
#pragma unroll
        for (int j = 0; j < 4; j++) {
            uint32_t pa[4];
            pa[0] = pack_bf16(sa[2 * j][0],     sa[2 * j][1]);
            pa[1] = pack_bf16(sa[2 * j][2],     sa[2 * j][3]);
            pa[2] = pack_bf16(sa[2 * j + 1][0], sa[2 * j + 1][1]);
            pa[3] = pack_bf16(sa[2 * j + 1][2], sa[2 * j + 1][3]);
            const uint32_t tOff = vOff + (uint32_t)(j * 16 * VROWB);
#pragma unroll
            for (int g = 0; g < 4; g++) {
                uint32_t vfh[4], vfl[4];
                ldsm4t(vfh, sb + AV_H + tOff + g * 32);
                ldsm4t(vfl, sb + AV_L + tOff + g * 32);
                mma16816(of[2 * g],     pa, vfh[0], vfh[1]);
                mma16816(of[2 * g + 1], pa, vfh[2], vfh[3]);
                mma16816(of[2 * g],     pa, vfl[0], vfl[1]);
                mma16816(of[2 * g + 1], pa, vfl[2], vfl[3]);
            }
        }
        __syncthreads();
    }

    // ---- epilogue: normalize, write tf32 fp32 ctx ----
    const float inv0 = 1.0f / l0, inv1 = 1.0f / l1;
    const int r0 = q0 + w * 16 + (lane >> 2);
#pragma unroll
    for (int nf = 0; nf < 8; nf++) {
        int d = nf * 8 + 2 * (lane & 3);
        size_t i0 = (size_t)r0 * DM + hcol + d;
        size_t i1 = (size_t)(r0 + 8) * DM + hcol + d;
        *(float2*)(ctx + i0) = make_float2(tf32r(of[nf][0] * inv0), tf32r(of[nf][1] * inv0));
        *(float2*)(ctx + i1) = make_float2(tf32r(of[nf][2] * inv1), tf32r(of[nf][3] * inv1));
    }
}

// ---------------------------------------------------------------------------
extern "C" void kernel_launch(void* const* d_in, const int* in_sizes, int n_in,
                              void* d_out, int out_size)
{
    const float* x   = (const float*)d_in[0];
    const float* Wq  = (const float*)d_in[1];
    const float* bq  = (const float*)d_in[2];
    const float* Wk  = (const float*)d_in[3];
    const float* bk  = (const float*)d_in[4];
    const float* Wv  = (const float*)d_in[5];
    const float* bv  = (const float*)d_in[6];
    const float* Wo  = (const float*)d_in[7];
    const float* bo  = (const float*)d_in[8];
    const float* l1s = (const float*)d_in[9];
    const float* l1b = (const float*)d_in[10];
    const float* l2s = (const float*)d_in[11];
    const float* l2b = (const float*)d_in[12];
    const float* W1  = (const float*)d_in[13];
    const float* b1  = (const float*)d_in[14];
    const float* W2  = (const float*)d_in[15];
    const float* b2  = (const float*)d_in[16];
    float* out = (float*)d_out;

    float *y, *qkbuf, *ctx, *y2, *hbuf, *wqkv, *wo, *w1, *w2, *bqkv;
    bf16 *vhb, *vlb;
    cudaGetSymbolAddress((void**)&y, g_y);
    cudaGetSymbolAddress((void**)&qkbuf, g_qk);
    cudaGetSymbolAddress((void**)&vhb, g_vh); cudaGetSymbolAddress((void**)&vlb, g_vl);
    cudaGetSymbolAddress((void**)&ctx, g_ctx);
    cudaGetSymbolAddress((void**)&y2, g_y2);
    cudaGetSymbolAddress((void**)&hbuf, g_h);
    cudaGetSymbolAddress((void**)&wqkv, g_wqkv);
    cudaGetSymbolAddress((void**)&wo, g_wo);
    cudaGetSymbolAddress((void**)&w1, g_w1);
    cudaGetSymbolAddress((void**)&w2, g_w2);
    cudaGetSymbolAddress((void**)&bqkv, g_bqkv);

    cudaFuncSetAttribute(attn_mix, cudaFuncAttributeMaxDynamicSharedMemorySize, ATTN_SMEM);
    cudaFuncSetAttribute(gemm_tf32<1>, cudaFuncAttributeMaxDynamicSharedMemorySize, GSMEM);
    cudaFuncSetAttribute(gemm_tf32<2>, cudaFuncAttributeMaxDynamicSharedMemorySize, GSMEM);
    cudaFuncSetAttribute(gemm_tf32<3>, cudaFuncAttributeMaxDynamicSharedMemorySize, GSMEM);

    // Launch order arranged so ncu (-s 5 -c 1) captures the QKV GEMM (launch #6).
    pack_bias<<<12, 256>>>(bq, bk, bv, bqkv);                 // 0
    ln_tf32<<<SQ, 256>>>(x, l1s, l1b, y);                     // 1 (LN1)
    wconv_t<<<dim3(32, 32), 256>>>(Wq, wqkv,             DM, DM);  // 2
    wconv_t<<<dim3(32, 32), 256>>>(Wk, wqkv + 1024 * DM, DM, DM);  // 3
    wconv_t<<<dim3(32, 32), 256>>>(Wv, wqkv + 2048 * DM, DM, DM);  // 4

    // 5: fused QKV -> QK tf32 fp32 (packed, q scaled) + V split bf16
    gemm_tf32<3><<<dim3(QKVN / 128, SQ / 128), 512, GSMEM>>>(
        y, wqkv, bqkv, nullptr, nullptr, qkbuf, vhb, vlb, QKVN, QKVN, DM);

    // remaining weight prep (independent of QKV result)
    wconv_t<<<dim3(32, 32), 256>>>(Wo, wo, DM, DM);            // 6
    wconv_t<<<dim3(128, 32), 256>>>(W1, w1, DM, FF);           // 7
    wconv_t<<<dim3(32, 128), 256>>>(W2, w2, FF, DM);           // 8

    // ---- attention (tf32 S + bf16-split PV) ----
    attn_mix<<<dim3(SQ / 128, NH), 256, ATTN_SMEM>>>(qkbuf, vhb, vlb, ctx);

    // ---- output projection + residual ----
    gemm_tf32<1><<<dim3(DM / 128, SQ / 128), 512, GSMEM>>>(
        ctx, wo, bo, x, out, nullptr, nullptr, nullptr, DM, DM, DM);

    // ---- LN2 ----
    ln_tf32<<<SQ, 256>>>(out, l2s, l2b, y2);

    // ---- FFN1 + GELU -> tf32 fp32 h ----
    gemm_tf32<2><<<dim3(FF / 128, SQ / 128), 512, GSMEM>>>(
        y2, w1, b1, nullptr, nullptr, hbuf, nullptr, nullptr, FF, FF, DM);

    // ---- FFN2 + residual (C==R aliasing safe) ----
    gemm_tf32<1><<<dim3(DM / 128, SQ / 128), 512, GSMEM>>>(
        hbuf, w2, b2, out, out, nullptr, nullptr, nullptr, DM, DM, FF);
}

// round 16
// speedup vs baseline: 2.2297x; 1.7548x over previous
#include <cuda_runtime.h>
#include <cuda_fp16.h>
#include <math.h>
#include <stdint.h>

#define SQ 4096
#define DM 1024
#define NH 16
#define DHD 64
#define FF 4096
#define QKVN 3072

// Scratch (device globals — no runtime allocation allowed)
__device__ __half g_y  [SQ*DM];      // LN1 out fp16
__device__ __half g_qkv[SQ*QKVN];    // packed q|k|v fp16 (q pre-scaled)
__device__ __half g_ctx[SQ*DM];      // attention out fp16
__device__ __half g_y2 [SQ*DM];      // LN2 out fp16
__device__ __half g_h  [SQ*FF];      // GELU out fp16
// transposed fp16 weights [N][K]
__device__ __half g_wqkv[QKVN*DM];
__device__ __half g_wo [DM*DM];
__device__ __half g_w1 [FF*DM];
__device__ __half g_w2 [DM*FF];
__device__ float g_bqkv[QKVN];

// ===========================================================================
// Helpers
// ===========================================================================
__device__ __forceinline__ uint32_t smem_u32(const void* p) {
    uint32_t a;
    asm("{ .reg .u64 t; cvta.to.shared.u64 t, %1; cvt.u32.u64 %0, t; }" : "=r"(a) : "l"(p));
    return a;
}
__device__ __forceinline__ void ldsm4(uint32_t* r, uint32_t addr) {
    asm volatile("ldmatrix.sync.aligned.m8n8.x4.shared.b16 {%0,%1,%2,%3}, [%4];"
        : "=r"(r[0]), "=r"(r[1]), "=r"(r[2]), "=r"(r[3]) : "r"(addr));
}
__device__ __forceinline__ void ldsm4t(uint32_t* r, uint32_t addr) {
    asm volatile("ldmatrix.sync.aligned.m8n8.x4.trans.shared.b16 {%0,%1,%2,%3}, [%4];"
        : "=r"(r[0]), "=r"(r[1]), "=r"(r[2]), "=r"(r[3]) : "r"(addr));
}
__device__ __forceinline__ void mma_f16(float* c, const uint32_t* a,
                                        uint32_t b0, uint32_t b1) {
    asm volatile("mma.sync.aligned.m16n8k16.row.col.f32.f16.f16.f32 "
        "{%0,%1,%2,%3}, {%4,%5,%6,%7}, {%8,%9}, {%0,%1,%2,%3};"
        : "+f"(c[0]), "+f"(c[1]), "+f"(c[2]), "+f"(c[3])
        : "r"(a[0]), "r"(a[1]), "r"(a[2]), "r"(a[3]), "r"(b0), "r"(b1));
}
__device__ __forceinline__ void cpasync16(uint32_t dst, const void* src) {
    asm volatile("cp.async.cg.shared.global [%0], [%1], 16;" :: "r"(dst), "l"(src));
}
#define CP_COMMIT() asm volatile("cp.async.commit_group;" ::: "memory")
#define CP_WAIT(n)  asm volatile("cp.async.wait_group %0;" :: "n"(n) : "memory")

__device__ __forceinline__ uint32_t pack_h2(float x0, float x1) {
    __half2 p = __floats2half2_rn(x0, x1);
    return *(uint32_t*)&p;
}

// ---------------------------------------------------------------------------
// Weight transpose + fp16: W[K][N] fp32 -> T[N][K] fp16
// ---------------------------------------------------------------------------
__global__ __launch_bounds__(256) void wconv_h(const float* __restrict__ W,
                                               __half* __restrict__ T,
                                               int K, int N)
{
    __shared__ float tile[32][33];
    const int n0 = blockIdx.x * 32, k0 = blockIdx.y * 32;
    const int t = threadIdx.x;
#pragma unroll
    for (int i = 0; i < 4; i++) {
        int idx = t + 256 * i;
        int kr = idx >> 5, nc = idx & 31;
        tile[kr][nc] = W[(size_t)(k0 + kr) * N + n0 + nc];
    }
    __syncthreads();
#pragma unroll
    for (int i = 0; i < 2; i++) {
        int idx = t + 256 * i;
        int n = idx >> 4, c = idx & 15;
        uint32_t hp = pack_h2(tile[2 * c][n], tile[2 * c + 1][n]);
        *(uint32_t*)(T + (size_t)(n0 + n) * K + k0 + 2 * c) = hp;
    }
}

__global__ void pack_bias(const float* __restrict__ bq, const float* __restrict__ bk,
                          const float* __restrict__ bv, float* __restrict__ dst)
{
    int i = blockIdx.x * 256 + threadIdx.x;
    if (i < 1024) dst[i] = bq[i];
    else if (i < 2048) dst[i] = bk[i - 1024];
    else if (i < QKVN) dst[i] = bv[i - 2048];
}

// ---------------------------------------------------------------------------
// LayerNorm -> fp16. One block/row, 256 threads.
// ---------------------------------------------------------------------------
__global__ __launch_bounds__(256) void ln_h(const float* __restrict__ x,
                                            const float* __restrict__ sc,
                                            const float* __restrict__ bi,
                                            __half* __restrict__ y)
{
    int row = blockIdx.x;
    const float* xr = x + (size_t)row * DM;
    int t = threadIdx.x;

    float4 v = *(const float4*)(xr + 4 * t);
    float s = v.x + v.y + v.z + v.w;

    __shared__ float red[8];
#pragma unroll
    for (int o = 16; o > 0; o >>= 1) s += __shfl_xor_sync(0xffffffffu, s, o);
    if ((t & 31) == 0) red[t >> 5] = s;
    __syncthreads();
    if (t < 32) {
        float r = (t < 8) ? red[t] : 0.f;
#pragma unroll
        for (int o = 4; o > 0; o >>= 1) r += __shfl_xor_sync(0xffffffffu, r, o);
        if (t == 0) red[0] = r;
    }
    __syncthreads();
    float mu = red[0] * (1.0f / DM);
    __syncthreads();

    float d0 = v.x - mu, d1 = v.y - mu, d2 = v.z - mu, d3 = v.w - mu;
    float vs = d0 * d0 + d1 * d1 + d2 * d2 + d3 * d3;
#pragma unroll
    for (int o = 16; o > 0; o >>= 1) vs += __shfl_xor_sync(0xffffffffu, vs, o);
    if ((t & 31) == 0) red[t >> 5] = vs;
    __syncthreads();
    if (t < 32) {
        float r = (t < 8) ? red[t] : 0.f;
#pragma unroll
        for (int o = 4; o > 0; o >>= 1) r += __shfl_xor_sync(0xffffffffu, r, o);
        if (t == 0) red[0] = r;
    }
    __syncthreads();
    float rstd = rsqrtf(red[0] * (1.0f / DM) + 1e-6f);

    float4 s4 = *(const float4*)(sc + 4 * t);
    float4 b4 = *(const float4*)(bi + 4 * t);
    uint32_t h0 = pack_h2(d0 * rstd * s4.x + b4.x, d1 * rstd * s4.y + b4.y);
    uint32_t h1 = pack_h2(d2 * rstd * s4.z + b4.z, d3 * rstd * s4.w + b4.w);
    *(uint2*)(y + (size_t)row * DM + 4 * t) = make_uint2(h0, h1);
}

// ---------------------------------------------------------------------------
// FP16 HMMA GEMM, cp.async 3-stage pipelined.
// A[M][K] fp16, B[N][K] fp16. Block tile 128x128, BK=64, 512 threads =
// 16 warps (4M x 4N), warp tile 32x32. smem row: 64 halfs (128B) + 16B pad
// = 144B stride (conflict-free ldsm).
// EPI: 1 = +bias+residual -> fp32 C
//      2 = +bias, GELU -> fp16 O (stride ostride)
//      3 = QKV: cols<1024 x0.125 -> fp16 O (stride ostride=3072)
// ---------------------------------------------------------------------------
#define GROWB 144u
#define GS_B  18432u            // 128 rows * 144B
#define GSTAGE 36864u
#define GSMEM  (3u * GSTAGE)    // 110592

template <int EPI>
__global__ __launch_bounds__(512, 1) void gemm_f16(
    const __half* __restrict__ A, const __half* __restrict__ B,
    const float* __restrict__ bias, const float* __restrict__ R,
    float* __restrict__ C, __half* __restrict__ O,
    int ostride, int N, int K)
{
    extern __shared__ char smem[];
    const uint32_t sb = smem_u32(smem);
    const int t = threadIdx.x;
    const int lane = t & 31, w = t >> 5;
    const int wm = w & 3, wn = w >> 2;
    const int row0 = blockIdx.y * 128, col0 = blockIdx.x * 128;

    uint32_t aOff[2];
#pragma unroll
    for (int i = 0; i < 2; i++) {
        int r = wm * 32 + i * 16 + (lane & 7) + 8 * ((lane >> 3) & 1);
        aOff[i] = (uint32_t)(r * GROWB + 16 * (lane >> 4));
    }
    uint32_t bOff[2];
#pragma unroll
    for (int jj = 0; jj < 2; jj++) {
        int n = wn * 32 + jj * 16 + (lane & 7) + 8 * (lane >> 4);
        bOff[jj] = (uint32_t)(n * GROWB + 16 * ((lane >> 3) & 1) * 2);
    }
    // NOTE: b-frag k16 layout needs 16B col pairs; recompute exactly as R11:
#pragma unroll
    for (int jj = 0; jj < 2; jj++) {
        int n = wn * 32 + jj * 16 + (lane & 7) + 8 * (lane >> 4);
        bOff[jj] = (uint32_t)(n * GROWB + 16 * ((lane >> 3) & 1));
    }

    auto load_tile = [&](int kc, int buf) {
        const uint32_t base = sb + (uint32_t)buf * GSTAGE;
        const int k0 = kc * 64;
#pragma unroll
        for (int i = 0; i < 2; i++) {
            int id = t + 512 * i;                 // 1024 16B-chunks per array
            int r = id >> 3, ch = id & 7;
            uint32_t d = base + (uint32_t)(r * GROWB + ch * 16);
            cpasync16(d,        A + (size_t)(row0 + r) * K + k0 + ch * 8);
            cpasync16(d + GS_B, B + (size_t)(col0 + r) * K + k0 + ch * 8);
        }
    };

    float acc[2][4][4] = {};

    const int nk = K >> 6;
    load_tile(0, 0); CP_COMMIT();
    load_tile(1, 1); CP_COMMIT();

    int buf = 0;
    for (int kc = 0; kc < nk; kc++) {
        CP_WAIT(1);
        __syncthreads();

        if (kc + 2 < nk) {
            int nb = buf + 2; if (nb >= 3) nb -= 3;
            load_tile(kc + 2, nb);
            CP_COMMIT();
        }

        const uint32_t bs = sb + (uint32_t)buf * GSTAGE;
#pragma unroll
        for (int ks = 0; ks < 4; ks++) {          // k16 steps within BK=64
            const uint32_t kb = ks * 32;          // 16 halfs = 32B
            uint32_t ah[2][4], bh[2][4];
#pragma unroll
            for (int i = 0; i < 2; i++)
                ldsm4(ah[i], bs + aOff[i] + kb);
#pragma unroll
            for (int jj = 0; jj < 2; jj++)
                ldsm4(bh[jj], bs + GS_B + bOff[jj] + kb);
#pragma unroll
            for (int i = 0; i < 2; i++)
#pragma unroll
                for (int j = 0; j < 4; j++) {
                    const int jj = j >> 1, e = (j & 1) * 2;
                    mma_f16(acc[i][j], ah[i], bh[jj][e], bh[jj][e + 1]);
                }
        }
        if (++buf >= 3) buf -= 3;
    }

    // --- epilogue ---
#pragma unroll
    for (int i = 0; i < 2; i++) {
#pragma unroll
        for (int j = 0; j < 4; j++) {
            int r = row0 + wm * 32 + i * 16 + (lane >> 2);
            int cg = col0 + wn * 32 + j * 8 + 2 * (lane & 3);
#pragma unroll
            for (int half = 0; half < 2; half++) {
                int rr = r + half * 8;
                float vx = acc[i][j][half * 2 + 0] + bias[cg];
                float vy = acc[i][j][half * 2 + 1] + bias[cg + 1];
                if (EPI == 1) {
                    size_t idx = (size_t)rr * N + cg;
                    float2 r2 = *(const float2*)(R + idx);
                    *(float2*)(C + idx) = make_float2(vx + r2.x, vy + r2.y);
                } else if (EPI == 2) {
                    vx = 0.5f * vx * (1.0f + erff(vx * 0.70710678118654752f));
                    vy = 0.5f * vy * (1.0f + erff(vy * 0.70710678118654752f));
                    *(uint32_t*)(O + (size_t)rr * ostride + cg) = pack_h2(vx, vy);
                } else {
                    if (cg < 1024) { vx *= 0.125f; vy *= 0.125f; }
                    *(uint32_t*)(O + (size_t)rr * ostride + cg) = pack_h2(vx, vy);
                }
            }
        }
    }
}

// ---------------------------------------------------------------------------
// FP16 flash attention over packed qkv (row stride 3072).
// Block = 128 q-rows x 1 head, 8 warps. kv tile 64. Output fp16 ctx.
// smem rows: 64 halfs + 16B pad = 144B stride.
// ---------------------------------------------------------------------------
#define TSTRB 144
#define AQ 0u
#define AK (128u * TSTRB)            // 18432
#define AV (AK + 64u * TSTRB)        // 27648
#define ATTN_SMEM (AV + 64u * TSTRB) // 36864

__global__ __launch_bounds__(256, 2) void attn_f16(
    const __half* __restrict__ qkv, __half* __restrict__ ctx)
{
    extern __shared__ char smem[];
    const uint32_t sb = smem_u32(smem);
    const int t = threadIdx.x;
    const int lane = t & 31, w = t >> 5;
    const int h = blockIdx.y;
    const int q0 = blockIdx.x * 128;
    const int hcol = h * DHD;

    // ---- load Q tile (128 x 64 fp16) ----
#pragma unroll
    for (int it = 0; it < 4; it++) {
        int idx = t + 256 * it;
        int r = idx >> 3, c = idx & 7;
        *(uint4*)(smem + AQ + r * TSTRB + c * 16) =
            *(const uint4*)(qkv + (size_t)(q0 + r) * QKVN + hcol + c * 8);
    }

    const uint32_t aOff = (uint32_t)((w * 16 + (lane & 15)) * TSTRB + 16 * (lane >> 4));
    uint32_t bOff[4];
#pragma unroll
    for (int ng = 0; ng < 4; ng++)
        bOff[ng] = (uint32_t)((ng * 16 + (lane & 7) + 8 * (lane >> 4)) * TSTRB
                              + 16 * ((lane >> 3) & 1));
    const uint32_t vOff = (uint32_t)(((lane & 7) + 8 * ((lane >> 3) & 1)) * TSTRB
                                     + 16 * (lane >> 4));

    float of[8][4] = {};
    float m0 = -1e30f, m1 = -1e30f, l0 = 0.f, l1 = 0.f;
    __syncthreads();

    for (int kb = 0; kb < SQ / 64; kb++) {
        const int k0 = kb * 64;

        // ---- load K + V tiles (64 x 64 fp16 each) ----
#pragma unroll
        for (int it = 0; it < 2; it++) {
            int idx = t + 256 * it;
            int r = idx >> 3, c = idx & 7;
            size_t gk = (size_t)(k0 + r) * QKVN + 1024 + hcol + c * 8;
            uint32_t so = (uint32_t)(r * TSTRB + c * 16);
            *(uint4*)(smem + AK + so) = *(const uint4*)(qkv + gk);
            *(uint4*)(smem + AV + so) = *(const uint4*)(qkv + gk + 1024);
        }
        __syncthreads();

        // ---- S = Q @ K^T (fp16, 4 k16-steps) ----
        float sa[8][4] = {};
#pragma unroll
        for (int ks = 0; ks < 4; ks++) {
            const uint32_t kbyte = ks * 32;
            uint32_t qf[4];
            ldsm4(qf, sb + AQ + aOff + kbyte);
#pragma unroll
            for (int ng = 0; ng < 4; ng++) {
                uint32_t kf[4];
                ldsm4(kf, sb + AK + bOff[ng] + kbyte);
                mma_f16(sa[2 * ng],     qf, kf[0], kf[1]);
                mma_f16(sa[2 * ng + 1], qf, kf[2], kf[3]);
            }
        }

        // ---- online softmax ----
        float mx0 = -1e30f, mx1 = -1e30f;
#pragma unroll
        for (int nf = 0; nf < 8; nf++) {
            mx0 = fmaxf(mx0, fmaxf(sa[nf][0], sa[nf][1]));
            mx1 = fmaxf(mx1, fmaxf(sa[nf][2], sa[nf][3]));
        }
#pragma unroll
        for (int o = 1; o <= 2; o <<= 1) {
            mx0 = fmaxf(mx0, __shfl_xor_sync(0xffffffffu, mx0, o));
            mx1 = fmaxf(mx1, __shfl_xor_sync(0xffffffffu, mx1, o));
        }
        float mn0 = fmaxf(m0, mx0), mn1 = fmaxf(m1, mx1);
        float al0 = __expf(m0 - mn0), al1 = __expf(m1 - mn1);
        m0 = mn0; m1 = mn1;
        float rs0 = 0.f, rs1 = 0.f;
#pragma unroll
        for (int nf = 0; nf < 8; nf++) {
            sa[nf][0] = __expf(sa[nf][0] - mn0);
            sa[nf][1] = __expf(sa[nf][1] - mn0);
            sa[nf][2] = __expf(sa[nf][2] - mn1);
            sa[nf][3] = __expf(sa[nf][3] - mn1);
            rs0 += sa[nf][0] + sa[nf][1];
            rs1 += sa[nf][2] + sa[nf][3];
        }
#pragma unroll
        for (int o = 1; o <= 2; o <<= 1) {
            rs0 += __shfl_xor_sync(0xffffffffu, rs0, o);
            rs1 += __shfl_xor_sync(0xffffffffu, rs1, o);
        }
        l0 = l0 * al0 + rs0;
        l1 = l1 * al1 + rs1;
#pragma unroll
        for (int nf = 0; nf < 8; nf++) {
            of[nf][0] *= al0; of[nf][1] *= al0;
            of[nf][2] *= al1; of[nf][3] *= al1;
        }

        // ---- O += P @ V (fp16) ----
#pragma unroll
        for (int j = 0; j < 4; j++) {
            uint32_t pa[4];
            pa[0] = pack_h2(sa[2 * j][0],     sa[2 * j][1]);
            pa[1] = pack_h2(sa[2 * j][2],     sa[2 * j][3]);
            pa[2] = pack_h2(sa[2 * j + 1][0], sa[2 * j + 1][1]);
            pa[3] = pack_h2(sa[2 * j + 1][2], sa[2 * j + 1][3]);
            const uint32_t tOff = vOff + (uint32_t)(j * 16 * TSTRB);
#pragma unroll
            for (int g = 0; g < 4; g++) {
                uint32_t vf[4];
                ldsm4t(vf, sb + AV + tOff + g * 32);
                mma_f16(of[2 * g],     pa, vf[0], vf[1]);
                mma_f16(of[2 * g + 1], pa, vf[2], vf[3]);
            }
        }
        __syncthreads();
    }

    // ---- epilogue: normalize, write fp16 ctx ----
    const float inv0 = 1.0f / l0, inv1 = 1.0f / l1;
    const int r0 = q0 + w * 16 + (lane >> 2);
#pragma unroll
    for (int nf = 0; nf < 8; nf++) {
        int d = nf * 8 + 2 * (lane & 3);
        *(uint32_t*)(ctx + (size_t)r0 * DM + hcol + d) =
            pack_h2(of[nf][0] * inv0, of[nf][1] * inv0);
        *(uint32_t*)(ctx + (size_t)(r0 + 8) * DM + hcol + d) =
            pack_h2(of[nf][2] * inv1, of[nf][3] * inv1);
    }
}

// ---------------------------------------------------------------------------
extern "C" void kernel_launch(void* const* d_in, const int* in_sizes, int n_in,
                              void* d_out, int out_size)
{
    const float* x   = (const float*)d_in[0];
    const float* Wq  = (const float*)d_in[1];
    const float* bq  = (const float*)d_in[2];
    const float* Wk  = (const float*)d_in[3];
    const float* bk  = (const float*)d_in[4];
    const float* Wv  = (const float*)d_in[5];
    const float* bv  = (const float*)d_in[6];
    const float* Wo  = (const float*)d_in[7];
    const float* bo  = (const float*)d_in[8];
    const float* l1s = (const float*)d_in[9];
    const float* l1b = (const float*)d_in[10];
    const float* l2s = (const float*)d_in[11];
    const float* l2b = (const float*)d_in[12];
    const float* W1  = (const float*)d_in[13];
    const float* b1  = (const float*)d_in[14];
    const float* W2  = (const float*)d_in[15];
    const float* b2  = (const float*)d_in[16];
    float* out = (float*)d_out;

    __half *y, *qkv, *ctx, *y2, *hbuf, *wqkv, *wo, *w1, *w2;
    float *bqkv;
    cudaGetSymbolAddress((void**)&y, g_y);
    cudaGetSymbolAddress((void**)&qkv, g_qkv);
    cudaGetSymbolAddress((void**)&ctx, g_ctx);
    cudaGetSymbolAddress((void**)&y2, g_y2);
    cudaGetSymbolAddress((void**)&hbuf, g_h);
    cudaGetSymbolAddress((void**)&wqkv, g_wqkv);
    cudaGetSymbolAddress((void**)&wo, g_wo);
    cudaGetSymbolAddress((void**)&w1, g_w1);
    cudaGetSymbolAddress((void**)&w2, g_w2);
    cudaGetSymbolAddress((void**)&bqkv, g_bqkv);

    cudaFuncSetAttribute(attn_f16, cudaFuncAttributeMaxDynamicSharedMemorySize, ATTN_SMEM);
    cudaFuncSetAttribute(gemm_f16<1>, cudaFuncAttributeMaxDynamicSharedMemorySize, GSMEM);
    cudaFuncSetAttribute(gemm_f16<2>, cudaFuncAttributeMaxDynamicSharedMemorySize, GSMEM);
    cudaFuncSetAttribute(gemm_f16<3>, cudaFuncAttributeMaxDynamicSharedMemorySize, GSMEM);

    // ---- weight prep (once per launch) ----
    pack_bias<<<12, 256>>>(bq, bk, bv, bqkv);
    ln_h<<<SQ, 256>>>(x, l1s, l1b, y);
    wconv_h<<<dim3(32, 32), 256>>>(Wq, wqkv,             DM, DM);
    wconv_h<<<dim3(32, 32), 256>>>(Wk, wqkv + 1024 * DM, DM, DM);
    wconv_h<<<dim3(32, 32), 256>>>(Wv, wqkv + 2048 * DM, DM, DM);

    // fused QKV -> packed fp16 qkv (q pre-scaled)
    gemm_f16<3><<<dim3(QKVN / 128, SQ / 128), 512, GSMEM>>>(
        y, wqkv, bqkv, nullptr, nullptr, qkv, QKVN, QKVN, DM);

    wconv_h<<<dim3(32, 32), 256>>>(Wo, wo, DM, DM);
    wconv_h<<<dim3(128, 32), 256>>>(W1, w1, DM, FF);   // [N=4096][K=1024]
    wconv_h<<<dim3(32, 128), 256>>>(W2, w2, FF, DM);   // [N=1024][K=4096]

    // ---- attention (fp16 HMMA flash) ----
    attn_f16<<<dim3(SQ / 128, NH), 256, ATTN_SMEM>>>(qkv, ctx);

    // ---- output projection + residual ----
    gemm_f16<1><<<dim3(DM / 128, SQ / 128), 512, GSMEM>>>(
        ctx, wo, bo, x, out, nullptr, DM, DM, DM);

    // ---- LN2 ----
    ln_h<<<SQ, 256>>>(out, l2s, l2b, y2);

    // ---- FFN1 + GELU -> fp16 h ----
    gemm_f16<2><<<dim3(FF / 128, SQ / 128), 512, GSMEM>>>(
        y2, w1, b1, nullptr, nullptr, hbuf, FF, FF, DM);

    // ---- FFN2 + residual (C==R aliasing safe) ----
    gemm_f16<1><<<dim3(DM / 128, SQ / 128), 512, GSMEM>>>(
        hbuf, w2, b2, out, out, nullptr, DM, DM, FF);
}

// round 17
// speedup vs baseline: 2.5121x; 1.1267x over previous
#include <cuda_runtime.h>
#include <cuda_fp16.h>
#include <math.h>
#include <stdint.h>

#define SQ 4096
#define DM 1024
#define NH 16
#define DHD 64
#define FF 4096
#define QKVN 3072

// Scratch (device globals — no runtime allocation allowed)
__device__ __half g_y  [SQ*DM];      // LN1 out fp16
__device__ __half g_qkv[SQ*QKVN];    // packed q|k|v fp16 (q pre-scaled)
__device__ __half g_ctx[SQ*DM];      // attention out fp16
__device__ __half g_y2 [SQ*DM];      // LN2 out fp16
__device__ __half g_h  [SQ*FF];      // GELU out fp16
// fp16 weights, native [K][N] layout
__device__ __half g_wqkv[DM*QKVN];   // [1024][3072] = q|k|v packed along N
__device__ __half g_wo [DM*DM];
__device__ __half g_w1 [DM*FF];
__device__ __half g_w2 [FF*DM];
__device__ float g_bqkv[QKVN];

// ===========================================================================
// Helpers
// ===========================================================================
__device__ __forceinline__ uint32_t smem_u32(const void* p) {
    uint32_t a;
    asm("{ .reg .u64 t; cvta.to.shared.u64 t, %1; cvt.u32.u64 %0, t; }" : "=r"(a) : "l"(p));
    return a;
}
__device__ __forceinline__ void ldsm4(uint32_t* r, uint32_t addr) {
    asm volatile("ldmatrix.sync.aligned.m8n8.x4.shared.b16 {%0,%1,%2,%3}, [%4];"
        : "=r"(r[0]), "=r"(r[1]), "=r"(r[2]), "=r"(r[3]) : "r"(addr));
}
__device__ __forceinline__ void ldsm4t(uint32_t* r, uint32_t addr) {
    asm volatile("ldmatrix.sync.aligned.m8n8.x4.trans.shared.b16 {%0,%1,%2,%3}, [%4];"
        : "=r"(r[0]), "=r"(r[1]), "=r"(r[2]), "=r"(r[3]) : "r"(addr));
}
__device__ __forceinline__ void mma_f16(float* c, const uint32_t* a,
                                        uint32_t b0, uint32_t b1) {
    asm volatile("mma.sync.aligned.m16n8k16.row.col.f32.f16.f16.f32 "
        "{%0,%1,%2,%3}, {%4,%5,%6,%7}, {%8,%9}, {%0,%1,%2,%3};"
        : "+f"(c[0]), "+f"(c[1]), "+f"(c[2]), "+f"(c[3])
        : "r"(a[0]), "r"(a[1]), "r"(a[2]), "r"(a[3]), "r"(b0), "r"(b1));
}
__device__ __forceinline__ void cpasync16(uint32_t dst, const void* src) {
    asm volatile("cp.async.cg.shared.global [%0], [%1], 16;" :: "r"(dst), "l"(src));
}
#define CP_COMMIT() asm volatile("cp.async.commit_group;" ::: "memory")
#define CP_WAIT(n)  asm volatile("cp.async.wait_group %0;" :: "n"(n) : "memory")

__device__ __forceinline__ uint32_t pack_h2(float x0, float x1) {
    __half2 p = __floats2half2_rn(x0, x1);
    return *(uint32_t*)&p;
}

// ---------------------------------------------------------------------------
// Weight convert (no transpose): W fp32 [K][N] -> T fp16 [K][ldT] (+col offset)
// Each thread: 8 elements (2 float4 reads, 1 uint4 write).
// ---------------------------------------------------------------------------
__global__ __launch_bounds__(256) void wcvt(const float* __restrict__ W,
                                            __half* __restrict__ T,
                                            int N, int ldT)
{
    size_t e = ((size_t)blockIdx.x * 256 + threadIdx.x) * 8;
    int row = (int)(e / N), col = (int)(e % N);
    float4 a = *(const float4*)(W + e);
    float4 b = *(const float4*)(W + e + 4);
    uint4 o;
    o.x = pack_h2(a.x, a.y);
    o.y = pack_h2(a.z, a.w);
    o.z = pack_h2(b.x, b.y);
    o.w = pack_h2(b.z, b.w);
    *(uint4*)(T + (size_t)row * ldT + col) = o;
}

__global__ void pack_bias(const float* __restrict__ bq, const float* __restrict__ bk,
                          const float* __restrict__ bv, float* __restrict__ dst)
{
    int i = blockIdx.x * 256 + threadIdx.x;
    if (i < 1024) dst[i] = bq[i];
    else if (i < 2048) dst[i] = bk[i - 1024];
    else if (i < QKVN) dst[i] = bv[i - 2048];
}

// ---------------------------------------------------------------------------
// LayerNorm -> fp16. One block/row, 256 threads.
// ---------------------------------------------------------------------------
__global__ __launch_bounds__(256) void ln_h(const float* __restrict__ x,
                                            const float* __restrict__ sc,
                                            const float* __restrict__ bi,
                                            __half* __restrict__ y)
{
    int row = blockIdx.x;
    const float* xr = x + (size_t)row * DM;
    int t = threadIdx.x;

    float4 v = *(const float4*)(xr + 4 * t);
    float s = v.x + v.y + v.z + v.w;

    __shared__ float red[8];
#pragma unroll
    for (int o = 16; o > 0; o >>= 1) s += __shfl_xor_sync(0xffffffffu, s, o);
    if ((t & 31) == 0) red[t >> 5] = s;
    __syncthreads();
    if (t < 32) {
        float r = (t < 8) ? red[t] : 0.f;
#pragma unroll
        for (int o = 4; o > 0; o >>= 1) r += __shfl_xor_sync(0xffffffffu, r, o);
        if (t == 0) red[0] = r;
    }
    __syncthreads();
    float mu = red[0] * (1.0f / DM);
    __syncthreads();

    float d0 = v.x - mu, d1 = v.y - mu, d2 = v.z - mu, d3 = v.w - mu;
    float vs = d0 * d0 + d1 * d1 + d2 * d2 + d3 * d3;
#pragma unroll
    for (int o = 16; o > 0; o >>= 1) vs += __shfl_xor_sync(0xffffffffu, vs, o);
    if ((t & 31) == 0) red[t >> 5] = vs;
    __syncthreads();
    if (t < 32) {
        float r = (t < 8) ? red[t] : 0.f;
#pragma unroll
        for (int o = 4; o > 0; o >>= 1) r += __shfl_xor_sync(0xffffffffu, r, o);
        if (t == 0) red[0] = r;
    }
    __syncthreads();
    float rstd = rsqrtf(red[0] * (1.0f / DM) + 1e-6f);

    float4 s4 = *(const float4*)(sc + 4 * t);
    float4 b4 = *(const float4*)(bi + 4 * t);
    uint32_t h0 = pack_h2(d0 * rstd * s4.x + b4.x, d1 * rstd * s4.y + b4.y);
    uint32_t h1 = pack_h2(d2 * rstd * s4.z + b4.z, d3 * rstd * s4.w + b4.w);
    *(uint2*)(y + (size_t)row * DM + 4 * t) = make_uint2(h0, h1);
}

// ---------------------------------------------------------------------------
// FP16 HMMA GEMM. A[M][K] fp16, B[K][N] fp16 (native layout, ldsm4t for frags).
// Block tile 128x128, BK=64, 256 threads = 8 warps (4M x 2N), warp tile 32x64.
// 2-stage cp.async, 2 CTAs/SM.
// A smem: 128 rows x 144B (64 halfs + pad). B smem: 64 k-rows x 272B (128 halfs + pad).
// EPI: 1 = +bias+residual -> fp32 C
//      2 = +bias, GELU -> fp16 O (stride ostride)
//      3 = QKV: cols<1024 x0.125 -> fp16 O (stride ostride=3072)
// ---------------------------------------------------------------------------
#define AROWB 144u
#define BROWB 272u
#define OFF_B 18432u                 // 128*144
#define GSTAGE 35840u                // 18432 + 64*272
#define GSMEM  (2u * GSTAGE)         // 71680

template <int EPI>
__global__ __launch_bounds__(256, 2) void gemm_f16(
    const __half* __restrict__ A, const __half* __restrict__ B,
    const float* __restrict__ bias, const float* __restrict__ R,
    float* __restrict__ C, __half* __restrict__ O,
    int ostride, int N, int K)
{
    extern __shared__ char smem[];
    const uint32_t sb = smem_u32(smem);
    const int t = threadIdx.x;
    const int lane = t & 31, w = t >> 5;
    const int wm = w & 3, wn = w >> 2;          // 4M x 2N warp grid
    const int row0 = blockIdx.y * 128, col0 = blockIdx.x * 128;

    // A frags (row-major [M][K], ldsm4): rows wm*32 + i*16 + ...
    uint32_t aOff[2];
#pragma unroll
    for (int i = 0; i < 2; i++) {
        int r = wm * 32 + i * 16 + (lane & 7) + 8 * ((lane >> 3) & 1);
        aOff[i] = (uint32_t)(r * AROWB + 16 * (lane >> 4));
    }
    // B frags (row-major [K][N], ldsm4t; V-pattern from attention PV):
    // rows k = (lane&7) + 8*((lane>>3)&1); col bytes = wn*128 + g*32 + 16*(lane>>4)
    const uint32_t bOffBase = (uint32_t)(((lane & 7) + 8 * ((lane >> 3) & 1)) * BROWB
                                         + wn * 128 + 16 * (lane >> 4));

    auto load_tile = [&](int kc, int buf) {
        const uint32_t base = sb + (uint32_t)buf * GSTAGE;
        const int k0 = kc * 64;
        // A: 128 rows x 8 chunks = 1024 chunks / 256 threads = 4
#pragma unroll
        for (int i = 0; i < 4; i++) {
            int id = t + 256 * i;
            int r = id >> 3, ch = id & 7;
            cpasync16(base + (uint32_t)(r * AROWB + ch * 16),
                      A + (size_t)(row0 + r) * K + k0 + ch * 8);
        }
        // B: 64 k-rows x 16 chunks = 1024 chunks / 256 threads = 4
#pragma unroll
        for (int i = 0; i < 4; i++) {
            int id = t + 256 * i;
            int r = id >> 4, ch = id & 15;
            cpasync16(base + OFF_B + (uint32_t)(r * BROWB + ch * 16),
                      B + (size_t)(k0 + r) * N + col0 + ch * 8);
        }
    };

    float acc[2][8][4] = {};

    const int nk = K >> 6;
    load_tile(0, 0);
    CP_COMMIT();

    for (int kc = 0; kc < nk; kc++) {
        if (kc + 1 < nk) {
            load_tile(kc + 1, (kc + 1) & 1);
            CP_COMMIT();
            CP_WAIT(1);
        } else {
            CP_WAIT(0);
        }
        __syncthreads();

        const uint32_t bs = sb + (uint32_t)(kc & 1) * GSTAGE;
#pragma unroll
        for (int ks = 0; ks < 4; ks++) {          // k16 steps within BK=64
            uint32_t ah[2][4];
#pragma unroll
            for (int i = 0; i < 2; i++)
                ldsm4(ah[i], bs + aOff[i] + ks * 32);
            const uint32_t bks = bs + OFF_B + bOffBase + (uint32_t)(ks * 16) * BROWB;
#pragma unroll
            for (int g = 0; g < 4; g++) {          // 16-col groups within 64
                uint32_t bh[4];
                ldsm4t(bh, bks + g * 32);
#pragma unroll
                for (int i = 0; i < 2; i++) {
                    mma_f16(acc[i][2 * g],     ah[i], bh[0], bh[1]);
                    mma_f16(acc[i][2 * g + 1], ah[i], bh[2], bh[3]);
                }
            }
        }
        __syncthreads();
    }

    // --- epilogue ---
#pragma unroll
    for (int i = 0; i < 2; i++) {
#pragma unroll
        for (int j = 0; j < 8; j++) {
            int r = row0 + wm * 32 + i * 16 + (lane >> 2);
            int cg = col0 + wn * 64 + (j >> 1) * 16 + (j & 1) * 8 + 2 * (lane & 3);
#pragma unroll
            for (int half = 0; half < 2; half++) {
                int rr = r + half * 8;
                float vx = acc[i][j][half * 2 + 0] + bias[cg];
                float vy = acc[i][j][half * 2 + 1] + bias[cg + 1];
                if (EPI == 1) {
                    size_t idx = (size_t)rr * N + cg;
                    float2 r2 = *(const float2*)(R + idx);
                    *(float2*)(C + idx) = make_float2(vx + r2.x, vy + r2.y);
                } else if (EPI == 2) {
                    vx = 0.5f * vx * (1.0f + erff(vx * 0.70710678118654752f));
                    vy = 0.5f * vy * (1.0f + erff(vy * 0.70710678118654752f));
                    *(uint32_t*)(O + (size_t)rr * ostride + cg) = pack_h2(vx, vy);
                } else {
                    if (cg < 1024) { vx *= 0.125f; vy *= 0.125f; }
                    *(uint32_t*)(O + (size_t)rr * ostride + cg) = pack_h2(vx, vy);
                }
            }
        }
    }
}

// ---------------------------------------------------------------------------
// FP16 flash attention over packed qkv (row stride 3072). (unchanged from R16)
// ---------------------------------------------------------------------------
#define TSTRB 144
#define AQ 0u
#define AK (128u * TSTRB)
#define AV (AK + 64u * TSTRB)
#define ATTN_SMEM (AV + 64u * TSTRB)

__global__ __launch_bounds__(256, 2) void attn_f16(
    const __half* __restrict__ qkv, __half* __restrict__ ctx)
{
    extern __shared__ char smem[];
    const uint32_t sb = smem_u32(smem);
    const int t = threadIdx.x;
    const int lane = t & 31, w = t >> 5;
    const int h = blockIdx.y;
    const int q0 = blockIdx.x * 128;
    const int hcol = h * DHD;

#pragma unroll
    for (int it = 0; it < 4; it++) {
        int idx = t + 256 * it;
        int r = idx >> 3, c = idx & 7;
        *(uint4*)(smem + AQ + r * TSTRB + c * 16) =
            *(const uint4*)(qkv + (size_t)(q0 + r) * QKVN + hcol + c * 8);
    }

    const uint32_t aOff = (uint32_t)((w * 16 + (lane & 15)) * TSTRB + 16 * (lane >> 4));
    uint32_t bOff[4];
#pragma unroll
    for (int ng = 0; ng < 4; ng++)
        bOff[ng] = (uint32_t)((ng * 16 + (lane & 7) + 8 * (lane >> 4)) * TSTRB
                              + 16 * ((lane >> 3) & 1));
    const uint32_t vOff = (uint32_t)(((lane & 7) + 8 * ((lane >> 3) & 1)) * TSTRB
                                     + 16 * (lane >> 4));

    float of[8][4] = {};
    float m0 = -1e30f, m1 = -1e30f, l0 = 0.f, l1 = 0.f;
    __syncthreads();

    for (int kb = 0; kb < SQ / 64; kb++) {
        const int k0 = kb * 64;

#pragma unroll
        for (int it = 0; it < 2; it++) {
            int idx = t + 256 * it;
            int r = idx >> 3, c = idx & 7;
            size_t gk = (size_t)(k0 + r) * QKVN + 1024 + hcol + c * 8;
            uint32_t so = (uint32_t)(r * TSTRB + c * 16);
            *(uint4*)(smem + AK + so) = *(const uint4*)(qkv + gk);
            *(uint4*)(smem + AV + so) = *(const uint4*)(qkv + gk + 1024);
        }
        __syncthreads();

        float sa[8][4] = {};
#pragma unroll
        for (int ks = 0; ks < 4; ks++) {
            const uint32_t kbyte = ks * 32;
            uint32_t qf[4];
            ldsm4(qf, sb + AQ + aOff + kbyte);
#pragma unroll
            for (int ng = 0; ng < 4; ng++) {
                uint32_t kf[4];
                ldsm4(kf, sb + AK + bOff[ng] + kbyte);
                mma_f16(sa[2 * ng],     qf, kf[0], kf[1]);
                mma_f16(sa[2 * ng + 1], qf, kf[2], kf[3]);
            }
        }

        float mx0 = -1e30f, mx1 = -1e30f;
#pragma unroll
        for (int nf = 0; nf < 8; nf++) {
            mx0 = fmaxf(mx0, fmaxf(sa[nf][0], sa[nf][1]));
            mx1 = fmaxf(mx1, fmaxf(sa[nf][2], sa[nf][3]));
        }
#pragma unroll
        for (int o = 1; o <= 2; o <<= 1) {
            mx0 = fmaxf(mx0, __shfl_xor_sync(0xffffffffu, mx0, o));
            mx1 = fmaxf(mx1, __shfl_xor_sync(0xffffffffu, mx1, o));
        }
        float mn0 = fmaxf(m0, mx0), mn1 = fmaxf(m1, mx1);
        float al0 = __expf(m0 - mn0), al1 = __expf(m1 - mn1);
        m0 = mn0; m1 = mn1;
        float rs0 = 0.f, rs1 = 0.f;
#pragma unroll
        for (int nf = 0; nf < 8; nf++) {
            sa[nf][0] = __expf(sa[nf][0] - mn0);
            sa[nf][1] = __expf(sa[nf][1] - mn0);
            sa[nf][2] = __expf(sa[nf][2] - mn1);
            sa[nf][3] = __expf(sa[nf][3] - mn1);
            rs0 += sa[nf][0] + sa[nf][1];
            rs1 += sa[nf][2] + sa[nf][3];
        }
#pragma unroll
        for (int o = 1; o <= 2; o <<= 1) {
            rs0 += __shfl_xor_sync(0xffffffffu, rs0, o);
            rs1 += __shfl_xor_sync(0xffffffffu, rs1, o);
        }
        l0 = l0 * al0 + rs0;
        l1 = l1 * al1 + rs1;
#pragma unroll
        for (int nf = 0; nf < 8; nf++) {
            of[nf][0] *= al0; of[nf][1] *= al0;
            of[nf][2] *= al1; of[nf][3] *= al1;
        }

#pragma unroll
        for (int j = 0; j < 4; j++) {
            uint32_t pa[4];
            pa[0] = pack_h2(sa[2 * j][0],     sa[2 * j][1]);
            pa[1] = pack_h2(sa[2 * j][2],     sa[2 * j][3]);
            pa[2] = pack_h2(sa[2 * j + 1][0], sa[2 * j + 1][1]);
            pa[3] = pack_h2(sa[2 * j + 1][2], sa[2 * j + 1][3]);
            const uint32_t tOff = vOff + (uint32_t)(j * 16 * TSTRB);
#pragma unroll
            for (int g = 0; g < 4; g++) {
                uint32_t vf[4];
                ldsm4t(vf, sb + AV + tOff + g * 32);
                mma_f16(of[2 * g],     pa, vf[0], vf[1]);
                mma_f16(of[2 * g + 1], pa, vf[2], vf[3]);
            }
        }
        __syncthreads();
    }

    const float inv0 = 1.0f / l0, inv1 = 1.0f / l1;
    const int r0 = q0 + w * 16 + (lane >> 2);
#pragma unroll
    for (int nf = 0; nf < 8; nf++) {
        int d = nf * 8 + 2 * (lane & 3);
        *(uint32_t*)(ctx + (size_t)r0 * DM + hcol + d) =
            pack_h2(of[nf][0] * inv0, of[nf][1] * inv0);
        *(uint32_t*)(ctx + (size_t)(r0 + 8) * DM + hcol + d) =
            pack_h2(of[nf][2] * inv1, of[nf][3] * inv1);
    }
}

// ---------------------------------------------------------------------------
extern "C" void kernel_launch(void* const* d_in, const int* in_sizes, int n_in,
                              void* d_out, int out_size)
{
    const float* x   = (const float*)d_in[0];
    const float* Wq  = (const float*)d_in[1];
    const float* bq  = (const float*)d_in[2];
    const float* Wk  = (const float*)d_in[3];
    const float* bk  = (const float*)d_in[4];
    const float* Wv  = (const float*)d_in[5];
    const float* bv  = (const float*)d_in[6];
    const float* Wo  = (const float*)d_in[7];
    const float* bo  = (const float*)d_in[8];
    const float* l1s = (const float*)d_in[9];
    const float* l1b = (const float*)d_in[10];
    const float* l2s = (const float*)d_in[11];
    const float* l2b = (const float*)d_in[12];
    const float* W1  = (const float*)d_in[13];
    const float* b1  = (const float*)d_in[14];
    const float* W2  = (const float*)d_in[15];
    const float* b2  = (const float*)d_in[16];
    float* out = (float*)d_out;

    __half *y, *qkv, *ctx, *y2, *hbuf, *wqkv, *wo, *w1, *w2;
    float *bqkv;
    cudaGetSymbolAddress((void**)&y, g_y);
    cudaGetSymbolAddress((void**)&qkv, g_qkv);
    cudaGetSymbolAddress((void**)&ctx, g_ctx);
    cudaGetSymbolAddress((void**)&y2, g_y2);
    cudaGetSymbolAddress((void**)&hbuf, g_h);
    cudaGetSymbolAddress((void**)&wqkv, g_wqkv);
    cudaGetSymbolAddress((void**)&wo, g_wo);
    cudaGetSymbolAddress((void**)&w1, g_w1);
    cudaGetSymbolAddress((void**)&w2, g_w2);
    cudaGetSymbolAddress((void**)&bqkv, g_bqkv);

    cudaFuncSetAttribute(attn_f16, cudaFuncAttributeMaxDynamicSharedMemorySize, ATTN_SMEM);
    cudaFuncSetAttribute(gemm_f16<1>, cudaFuncAttributeMaxDynamicSharedMemorySize, GSMEM);
    cudaFuncSetAttribute(gemm_f16<2>, cudaFuncAttributeMaxDynamicSharedMemorySize, GSMEM);
    cudaFuncSetAttribute(gemm_f16<3>, cudaFuncAttributeMaxDynamicSharedMemorySize, GSMEM);

    // ---- weight prep: pure fp32->fp16 copies into packed/native layouts ----
    pack_bias<<<12, 256>>>(bq, bk, bv, bqkv);
    ln_h<<<SQ, 256>>>(x, l1s, l1b, y);
    wcvt<<<DM * DM / (256 * 8), 256>>>(Wq, wqkv,        DM, QKVN);   // [1024][3072] cols 0..1023
    wcvt<<<DM * DM / (256 * 8), 256>>>(Wk, wqkv + 1024, DM, QKVN);   // cols 1024..2047
    wcvt<<<DM * DM / (256 * 8), 256>>>(Wv, wqkv + 2048, DM, QKVN);   // cols 2048..3071

    // fused QKV -> packed fp16 qkv (q pre-scaled)
    gemm_f16<3><<<dim3(QKVN / 128, SQ / 128), 256, GSMEM>>>(
        y, wqkv, bqkv, nullptr, nullptr, qkv, QKVN, QKVN, DM);

    wcvt<<<DM * DM / (256 * 8), 256>>>(Wo, wo, DM, DM);
    wcvt<<<DM * FF / (256 * 8), 256>>>(W1, w1, FF, FF);
    wcvt<<<FF * DM / (256 * 8), 256>>>(W2, w2, DM, DM);

    // ---- attention (fp16 HMMA flash) ----
    attn_f16<<<dim3(SQ / 128, NH), 256, ATTN_SMEM>>>(qkv, ctx);

    // ---- output projection + residual ----
    gemm_f16<1><<<dim3(DM / 128, SQ / 128), 256, GSMEM>>>(
        ctx, wo, bo, x, out, nullptr, DM, DM, DM);

    // ---- LN2 ----
    ln_h<<<SQ, 256>>>(out, l2s, l2b, y2);

    // ---- FFN1 + GELU -> fp16 h ----
    gemm_f16<2><<<dim3(FF / 128, SQ / 128), 256, GSMEM>>>(
        y2, w1, b1, nullptr, nullptr, hbuf, FF, FF, DM);

    // ---- FFN2 + residual (C==R aliasing safe) ----
    gemm_f16<1><<<dim3(DM / 128, SQ / 128), 256, GSMEM>>>(
        hbuf, w2, b2, out, out, nullptr, DM, DM, FF);
}